// round 3
// baseline (speedup 1.0000x reference)
#include <cuda_runtime.h>
#include <cuda_bf16.h>
#include <math.h>

// Problem constants
#define B_  16384
#define F_  32
#define D_  64
#define IN_ 2048   // F_*D_
#define EPS_ 1e-5f

typedef unsigned long long u64;

// ---- packed f32x2 helpers (sm_100+: fma.rn.f32x2, PTX-only) ----
__device__ __forceinline__ u64 pk2(float v) {
    u64 r; asm("mov.b64 %0,{%1,%1};" : "=l"(r) : "f"(v)); return r;
}
__device__ __forceinline__ void fma2(u64& d, u64 a, u64 b) {
    asm("fma.rn.f32x2 %0,%1,%2,%0;" : "+l"(d) : "l"(a), "l"(b));
}
__device__ __forceinline__ float2 up2(u64 v) {
    float2 f; asm("mov.b64 {%0,%1},%2;" : "=f"(f.x), "=f"(f.y) : "l"(v)); return f;
}

// ---------------------------------------------------------------------------
// Scratch (no device mallocs allowed)
// ---------------------------------------------------------------------------
__device__ float g_mask_buf[(size_t)B_ * F_];
__device__ float g_vbuf[(size_t)F_ * B_ * D_];

// ===========================================================================
// Kernel 1: mask branch. BM=64, 128 threads, 256 CTAs, packed-f32x2 mainloop.
// Thread tile: 8 rows x 6 cols (3 packed col-pairs).
// ===========================================================================
#define BM 64
#define BK 32
#define AS_STRIDE 36
#define BS_STRIDE 100
#define CS_STRIDE 97
// As 64*36 + Bs 32*100 + Cs 64*97 + mw2s 2048 + mgws 1024 + mlw2s 1024 + 256
#define K1_SMEM_FLOATS (BM*AS_STRIDE + BK*BS_STRIDE + BM*CS_STRIDE + 2048 + 1024 + 1024 + 256)

__global__ __launch_bounds__(128, 3)
void k1_mask_kernel(const float* __restrict__ x,
                    const float* __restrict__ mw1, const float* __restrict__ mb1,
                    const float* __restrict__ mw2, const float* __restrict__ mb2,
                    const float* __restrict__ mlw, const float* __restrict__ mlb,
                    const float* __restrict__ mgw, const float* __restrict__ mgb,
                    const float* __restrict__ mlw2, const float* __restrict__ mlb2,
                    const float* __restrict__ mgamma, const float* __restrict__ mbeta,
                    float* __restrict__ gmask, float* __restrict__ out_mask)
{
    extern __shared__ float sm[];
    float* As    = sm;                       // [64][36]
    float* Bs    = As  + BM * AS_STRIDE;     // [32][100]
    float* Cs    = Bs  + BK * BS_STRIDE;     // [64][97]
    float* mw2s  = Cs  + BM * CS_STRIDE;     // [64][32]
    float* mgws  = mw2s + 2048;              // [32][32]
    float* mlw2s = mgws + 1024;              // [32][32]
    float* mb1s  = mlw2s + 1024;             // 64
    float* mb2s  = mb1s + 64;                // 32 each below
    float* mgbs  = mb2s + 32;
    float* mlb2s = mgbs + 32;
    float* mlbs  = mlb2s + 32;
    float* mgammas = mlbs + 32;
    float* mbetas  = mgammas + 32;

    const int tid = threadIdx.x;
    const int ty  = tid >> 4;        // 0..7  -> rows ty*8..ty*8+7
    const int tx  = tid & 15;        // 0..15 -> cols tx*6..tx*6+5
    const int m0  = blockIdx.x * BM;

    for (int i = tid; i < 2048; i += 128) mw2s[i] = mw2[i];
    for (int i = tid; i < 1024; i += 128) { mgws[i] = mgw[i]; mlw2s[i] = mlw2[i]; }
    if (tid < 64) mb1s[tid] = mb1[tid];
    if (tid < 32) {
        mb2s[tid]  = mb2[tid];  mgbs[tid] = mgb[tid];  mlb2s[tid] = mlb2[tid];
        mlbs[tid]  = mlb[tid];  mgammas[tid] = mgamma[tid]; mbetas[tid] = mbeta[tid];
    }

    u64 c2[8][3];
#pragma unroll
    for (int i = 0; i < 8; i++)
#pragma unroll
        for (int j = 0; j < 3; j++) c2[i][j] = 0ull;

    const int ar  = tid >> 3;        // 0..15
    const int ac  = (tid & 7) * 4;   // 0..28
    const int br  = tid >> 2;        // 0..31
    const int bq  = tid & 3;         // 0..3

    for (int k0 = 0; k0 < IN_; k0 += BK) {
        __syncthreads();
        // A tile: 64 x 32
#pragma unroll
        for (int p = 0; p < 4; p++) {
            int m = ar + 16 * p;
            float4 v = *(const float4*)&x[(size_t)(m0 + m) * IN_ + k0 + ac];
            *(float4*)&As[m * AS_STRIDE + ac] = v;
        }
        // B tile: 32 x 96 (mw1 cols 0..63, mlw cols 64..95)
#pragma unroll
        for (int q = 0; q < 6; q++) {
            int c4  = bq * 6 + q;   // 0..23
            int col = c4 * 4;
            float4 v;
            if (col < 64) v = *(const float4*)&mw1[(size_t)(k0 + br) * 64 + col];
            else          v = *(const float4*)&mlw[(size_t)(k0 + br) * 32 + (col - 64)];
            *(float4*)&Bs[br * BS_STRIDE + col] = v;
        }
        __syncthreads();

#pragma unroll
        for (int k = 0; k < BK; k++) {
            u64 b0 = *(const u64*)&Bs[k * BS_STRIDE + tx * 6];
            u64 b1 = *(const u64*)&Bs[k * BS_STRIDE + tx * 6 + 2];
            u64 b2 = *(const u64*)&Bs[k * BS_STRIDE + tx * 6 + 4];
#pragma unroll
            for (int i = 0; i < 8; i++) {
                u64 ap = pk2(As[(ty * 8 + i) * AS_STRIDE + k]);
                fma2(c2[i][0], ap, b0);
                fma2(c2[i][1], ap, b1);
                fma2(c2[i][2], ap, b2);
            }
        }
    }
    __syncthreads();
#pragma unroll
    for (int i = 0; i < 8; i++) {
        float* dst = &Cs[(ty * 8 + i) * CS_STRIDE + tx * 6];
        float2 v0 = up2(c2[i][0]), v1 = up2(c2[i][1]), v2 = up2(c2[i][2]);
        dst[0] = v0.x; dst[1] = v0.y; dst[2] = v1.x;
        dst[3] = v1.y; dst[4] = v2.x; dst[5] = v2.y;
    }
    __syncthreads();

    // per-row epilogue: threads 0..63 own row tid
    if (tid < BM) {
        const int base = tid * CS_STRIDE;
        const size_t gr = (size_t)(m0 + tid);

#pragma unroll 4
        for (int e = 0; e < 64; e++) {
            float v = Cs[base + e] + mb1s[e];
            Cs[base + e] = v > 0.f ? v : (__expf(v) - 1.0f);
        }
        float h[32];
#pragma unroll
        for (int j = 0; j < 32; j++) h[j] = mb2s[j];
#pragma unroll 4
        for (int e = 0; e < 64; e++) {
            float ev = Cs[base + e];
#pragma unroll
            for (int j = 0; j < 32; j++) h[j] = fmaf(ev, mw2s[e * 32 + j], h[j]);
        }
#pragma unroll
        for (int j = 0; j < 32; j++) Cs[base + j] = h[j];

        float g[32], l[32];
#pragma unroll
        for (int j = 0; j < 32; j++) { g[j] = mgbs[j]; l[j] = mlb2s[j]; }
#pragma unroll 2
        for (int i = 0; i < 32; i++) {
            float hv = Cs[base + i];
#pragma unroll
            for (int j = 0; j < 32; j++) {
                g[j] = fmaf(hv, mgws[i * 32 + j], g[j]);
                l[j] = fmaf(hv, mlw2s[i * 32 + j], l[j]);
            }
        }
        float pre[32];
#pragma unroll
        for (int j = 0; j < 32; j++) {
            float sig = 1.f / (1.f + __expf(-g[j]));
            pre[j] = fmaf(sig, l[j], Cs[base + 64 + j] + mlbs[j]);
        }
        float mean = 0.f;
#pragma unroll
        for (int j = 0; j < 32; j++) mean += pre[j];
        mean *= (1.f / 32.f);
        float var = 0.f;
#pragma unroll
        for (int j = 0; j < 32; j++) { float d = pre[j] - mean; var = fmaf(d, d, var); }
        var *= (1.f / 32.f);
        float inv = rsqrtf(var + EPS_);
        float mx = -3.4e38f;
#pragma unroll
        for (int j = 0; j < 32; j++) {
            pre[j] = fmaf((pre[j] - mean) * inv, mgammas[j], mbetas[j]);
            mx = fmaxf(mx, pre[j]);
        }
        float ssum = 0.f;
#pragma unroll
        for (int j = 0; j < 32; j++) { pre[j] = __expf(pre[j] - mx); ssum += pre[j]; }
        float rinv = 1.f / ssum;
#pragma unroll
        for (int j = 0; j < 32; j++) {
            float mv = pre[j] * rinv;
            gmask[gr * 32 + j] = mv;
            if (out_mask) out_mask[gr * 32 + j] = mv;
        }
    }
}

// ===========================================================================
// Kernel 2: feature-per-CTA GRN chain, packed-f32x2 mainloops.
// grid = F * (B/128) = 4096 CTAs, 256 threads, 2 CTAs/SM.
// Stage1/2: 4 rows x 8 cols (4 packed pairs). Stage3/4: two half-passes of
// 2 rows each with fused ga/la accumulation (keeps regs <= 128).
// ===========================================================================
#define R2   128
#define T2   256
#define XSTR 68
#define K2_SMEM_FLOATS (4096 + 4096 + R2*XSTR + R2*XSTR + 384 + 128)

__global__ __launch_bounds__(T2, 2)
void k2_grn_kernel(const float* __restrict__ x,
                   const float* __restrict__ w1, const float* __restrict__ b1,
                   const float* __restrict__ w2, const float* __restrict__ b2,
                   const float* __restrict__ gw, const float* __restrict__ gb,
                   const float* __restrict__ lw, const float* __restrict__ lb,
                   const float* __restrict__ gamma, const float* __restrict__ beta,
                   const float* __restrict__ gmask, float* __restrict__ vbuf)
{
    extern __shared__ float sm[];
    float* w0s  = sm;                 // 4096: w1, later gw
    float* w1s  = w0s + 4096;         // 4096: w2, later lw
    float* xs   = w1s + 4096;         // [128][XSTR]
    float* hhs  = xs  + R2 * XSTR;    // [128][XSTR]
    float* bias = hhs + R2 * XSTR;    // b1,b2,gb,lb,gamma,beta (64 each)
    float* msk  = bias + 384;         // 128

    const int tid = threadIdx.x;
    const int f   = blockIdx.x >> 7;
    const int rb  = blockIdx.x & 127;
    const int r0  = rb * R2;
    const size_t wo = (size_t)f * 4096;

#pragma unroll
    for (int q = 0; q < 4; q++) {
        int i4 = tid + T2 * q;
        ((float4*)w0s)[i4] = ((const float4*)(w1 + wo))[i4];
        ((float4*)w1s)[i4] = ((const float4*)(w2 + wo))[i4];
    }
#pragma unroll
    for (int q = 0; q < 8; q++) {
        int j   = tid + T2 * q;
        int row = j >> 4;
        int dg  = j & 15;
        float4 v = *(const float4*)&x[((size_t)(r0 + row) * F_ + f) * 64 + dg * 4];
        *(float4*)&xs[row * XSTR + dg * 4] = v;
    }
    if (tid < 64) {
        bias[tid]       = b1[f * 64 + tid];
        bias[64 + tid]  = b2[f * 64 + tid];
        bias[128 + tid] = gb[f * 64 + tid];
        bias[192 + tid] = lb[f * 64 + tid];
        bias[256 + tid] = gamma[f * 64 + tid];
        bias[320 + tid] = beta[f * 64 + tid];
    }
    if (tid < 128) msk[tid] = gmask[(size_t)(r0 + tid) * F_ + f];
    __syncthreads();

    const int ty = tid >> 3;       // 0..31
    const int tx = tid & 7;        // 0..7
    const int Rr = ty * 4;
    const int Cc = tx * 8;

    u64 acc2[4][4];

    // ================= stage 1: hh1 = elu(x @ w1 + b1) =================
    {
        ulonglong2 bA = *(const ulonglong2*)&bias[Cc];
        ulonglong2 bB = *(const ulonglong2*)&bias[Cc + 4];
#pragma unroll
        for (int i = 0; i < 4; i++) {
            acc2[i][0] = bA.x; acc2[i][1] = bA.y; acc2[i][2] = bB.x; acc2[i][3] = bB.y;
        }
        for (int d = 0; d < 64; d += 4) {
            float4 a4[4];
#pragma unroll
            for (int i = 0; i < 4; i++) a4[i] = *(float4*)&xs[(Rr + i) * XSTR + d];
#pragma unroll
            for (int dd = 0; dd < 4; dd++) {
                ulonglong2 wA = *(const ulonglong2*)&w0s[(d + dd) * 64 + Cc];
                ulonglong2 wB = *(const ulonglong2*)&w0s[(d + dd) * 64 + Cc + 4];
#pragma unroll
                for (int i = 0; i < 4; i++) {
                    float av = (dd == 0) ? a4[i].x : (dd == 1) ? a4[i].y : (dd == 2) ? a4[i].z : a4[i].w;
                    u64 ap = pk2(av);
                    fma2(acc2[i][0], ap, wA.x);
                    fma2(acc2[i][1], ap, wA.y);
                    fma2(acc2[i][2], ap, wB.x);
                    fma2(acc2[i][3], ap, wB.y);
                }
            }
        }
#pragma unroll
        for (int i = 0; i < 4; i++) {
            float2 v0 = up2(acc2[i][0]), v1 = up2(acc2[i][1]);
            float2 v2 = up2(acc2[i][2]), v3 = up2(acc2[i][3]);
            v0.x = v0.x > 0.f ? v0.x : (__expf(v0.x) - 1.f);
            v0.y = v0.y > 0.f ? v0.y : (__expf(v0.y) - 1.f);
            v1.x = v1.x > 0.f ? v1.x : (__expf(v1.x) - 1.f);
            v1.y = v1.y > 0.f ? v1.y : (__expf(v1.y) - 1.f);
            v2.x = v2.x > 0.f ? v2.x : (__expf(v2.x) - 1.f);
            v2.y = v2.y > 0.f ? v2.y : (__expf(v2.y) - 1.f);
            v3.x = v3.x > 0.f ? v3.x : (__expf(v3.x) - 1.f);
            v3.y = v3.y > 0.f ? v3.y : (__expf(v3.y) - 1.f);
            *(float4*)&hhs[(Rr + i) * XSTR + Cc]     = make_float4(v0.x, v0.y, v1.x, v1.y);
            *(float4*)&hhs[(Rr + i) * XSTR + Cc + 4] = make_float4(v2.x, v2.y, v3.x, v3.y);
        }
    }
    __syncthreads();

    // reload gw -> w0s
#pragma unroll
    for (int q = 0; q < 4; q++) {
        int i4 = tid + T2 * q;
        ((float4*)w0s)[i4] = ((const float4*)(gw + wo))[i4];
    }

    // ================= stage 2: hh2 = hh1 @ w2 + b2 =================
    {
        ulonglong2 bA = *(const ulonglong2*)&bias[64 + Cc];
        ulonglong2 bB = *(const ulonglong2*)&bias[64 + Cc + 4];
#pragma unroll
        for (int i = 0; i < 4; i++) {
            acc2[i][0] = bA.x; acc2[i][1] = bA.y; acc2[i][2] = bB.x; acc2[i][3] = bB.y;
        }
        for (int d = 0; d < 64; d += 4) {
            float4 a4[4];
#pragma unroll
            for (int i = 0; i < 4; i++) a4[i] = *(float4*)&hhs[(Rr + i) * XSTR + d];
#pragma unroll
            for (int dd = 0; dd < 4; dd++) {
                ulonglong2 wA = *(const ulonglong2*)&w1s[(d + dd) * 64 + Cc];
                ulonglong2 wB = *(const ulonglong2*)&w1s[(d + dd) * 64 + Cc + 4];
#pragma unroll
                for (int i = 0; i < 4; i++) {
                    float av = (dd == 0) ? a4[i].x : (dd == 1) ? a4[i].y : (dd == 2) ? a4[i].z : a4[i].w;
                    u64 ap = pk2(av);
                    fma2(acc2[i][0], ap, wA.x);
                    fma2(acc2[i][1], ap, wA.y);
                    fma2(acc2[i][2], ap, wB.x);
                    fma2(acc2[i][3], ap, wB.y);
                }
            }
        }
    }
    __syncthreads();

    // overwrite hhs with hh2; reload lw -> w1s
#pragma unroll
    for (int i = 0; i < 4; i++) {
        float2 v0 = up2(acc2[i][0]), v1 = up2(acc2[i][1]);
        float2 v2 = up2(acc2[i][2]), v3 = up2(acc2[i][3]);
        *(float4*)&hhs[(Rr + i) * XSTR + Cc]     = make_float4(v0.x, v0.y, v1.x, v1.y);
        *(float4*)&hhs[(Rr + i) * XSTR + Cc + 4] = make_float4(v2.x, v2.y, v3.x, v3.y);
    }
#pragma unroll
    for (int q = 0; q < 4; q++) {
        int i4 = tid + T2 * q;
        ((float4*)w1s)[i4] = ((const float4*)(lw + wo))[i4];
    }
    __syncthreads();

    // ============ stage 3+4 in two half-passes (2 rows each) ============
    {
        ulonglong2 gbA = *(const ulonglong2*)&bias[128 + Cc];
        ulonglong2 gbB = *(const ulonglong2*)&bias[128 + Cc + 4];
        ulonglong2 lbA = *(const ulonglong2*)&bias[192 + Cc];
        ulonglong2 lbB = *(const ulonglong2*)&bias[192 + Cc + 4];
        float4 gm0 = *(float4*)&bias[256 + Cc], gm1 = *(float4*)&bias[256 + Cc + 4];
        float4 bt0 = *(float4*)&bias[320 + Cc], bt1 = *(float4*)&bias[320 + Cc + 4];
        float gmv[8] = {gm0.x,gm0.y,gm0.z,gm0.w,gm1.x,gm1.y,gm1.z,gm1.w};
        float btv[8] = {bt0.x,bt0.y,bt0.z,bt0.w,bt1.x,bt1.y,bt1.z,bt1.w};

#pragma unroll
        for (int half = 0; half < 2; half++) {
            const int rI = Rr + half * 2;
            u64 ga2[2][4], la2[2][4];
#pragma unroll
            for (int r2 = 0; r2 < 2; r2++) {
                ga2[r2][0] = gbA.x; ga2[r2][1] = gbA.y; ga2[r2][2] = gbB.x; ga2[r2][3] = gbB.y;
                la2[r2][0] = lbA.x; la2[r2][1] = lbA.y; la2[r2][2] = lbB.x; la2[r2][3] = lbB.y;
            }
            for (int d = 0; d < 64; d += 4) {
                float4 a4[2];
                a4[0] = *(float4*)&hhs[(rI    ) * XSTR + d];
                a4[1] = *(float4*)&hhs[(rI + 1) * XSTR + d];
#pragma unroll
                for (int dd = 0; dd < 4; dd++) {
                    ulonglong2 gA = *(const ulonglong2*)&w0s[(d + dd) * 64 + Cc];
                    ulonglong2 gB = *(const ulonglong2*)&w0s[(d + dd) * 64 + Cc + 4];
                    ulonglong2 lA = *(const ulonglong2*)&w1s[(d + dd) * 64 + Cc];
                    ulonglong2 lB = *(const ulonglong2*)&w1s[(d + dd) * 64 + Cc + 4];
#pragma unroll
                    for (int r2 = 0; r2 < 2; r2++) {
                        float av = (dd == 0) ? a4[r2].x : (dd == 1) ? a4[r2].y : (dd == 2) ? a4[r2].z : a4[r2].w;
                        u64 ap = pk2(av);
                        fma2(ga2[r2][0], ap, gA.x);
                        fma2(ga2[r2][1], ap, gA.y);
                        fma2(ga2[r2][2], ap, gB.x);
                        fma2(ga2[r2][3], ap, gB.y);
                        fma2(la2[r2][0], ap, lA.x);
                        fma2(la2[r2][1], ap, lA.y);
                        fma2(la2[r2][2], ap, lB.x);
                        fma2(la2[r2][3], ap, lB.y);
                    }
                }
            }
            // epilogue per row
#pragma unroll
            for (int r2 = 0; r2 < 2; r2++) {
                const int row = rI + r2;
                float ga[8], la[8];
                {
                    float2 t;
                    t = up2(ga2[r2][0]); ga[0] = t.x; ga[1] = t.y;
                    t = up2(ga2[r2][1]); ga[2] = t.x; ga[3] = t.y;
                    t = up2(ga2[r2][2]); ga[4] = t.x; ga[5] = t.y;
                    t = up2(ga2[r2][3]); ga[6] = t.x; ga[7] = t.y;
                    t = up2(la2[r2][0]); la[0] = t.x; la[1] = t.y;
                    t = up2(la2[r2][1]); la[2] = t.x; la[3] = t.y;
                    t = up2(la2[r2][2]); la[4] = t.x; la[5] = t.y;
                    t = up2(la2[r2][3]); la[6] = t.x; la[7] = t.y;
                }
                float4 x0 = *(float4*)&xs[row * XSTR + Cc];
                float4 x1 = *(float4*)&xs[row * XSTR + Cc + 4];
                float xr[8] = {x0.x,x0.y,x0.z,x0.w,x1.x,x1.y,x1.z,x1.w};
                float yv[8];
                float s1 = 0.f, s2 = 0.f;
#pragma unroll
                for (int j = 0; j < 8; j++) {
                    float sig = 1.f / (1.f + __expf(-ga[j]));
                    float v = fmaf(sig, la[j], xr[j]);
                    yv[j] = v;
                    s1 += v;
                    s2 = fmaf(v, v, s2);
                }
#pragma unroll
                for (int o = 1; o < 8; o <<= 1) {
                    s1 += __shfl_xor_sync(0xFFFFFFFFu, s1, o);
                    s2 += __shfl_xor_sync(0xFFFFFFFFu, s2, o);
                }
                float mean = s1 * (1.f / 64.f);
                float var  = fmaf(-mean, mean, s2 * (1.f / 64.f));
                float inv  = rsqrtf(var + EPS_);
                float mv   = msk[row];
                float o0[8];
#pragma unroll
                for (int j = 0; j < 8; j++)
                    o0[j] = mv * fmaf((yv[j] - mean) * inv, gmv[j], btv[j]);
                float* dst = &vbuf[((size_t)f * B_ + (size_t)(r0 + row)) * 64 + Cc];
                *(float4*)dst       = make_float4(o0[0], o0[1], o0[2], o0[3]);
                *(float4*)(dst + 4) = make_float4(o0[4], o0[5], o0[6], o0[7]);
            }
        }
    }
}

// ===========================================================================
// Kernel 3: out[b,d] = sum_f vbuf[f,b,d]. Pure bandwidth (~268MB).
// ===========================================================================
#define K3_T 256
__global__ __launch_bounds__(K3_T, 4)
void k3_reduce_kernel(const float* __restrict__ vbuf, float* __restrict__ out)
{
    const size_t i4 = (size_t)blockIdx.x * K3_T + threadIdx.x;
    const size_t stride4 = (size_t)B_ * D_ / 4;
    const float4* vb = (const float4*)vbuf;
    float4 a = vb[i4];
#pragma unroll 4
    for (int f = 1; f < F_; f++) {
        float4 v = vb[i4 + (size_t)f * stride4];
        a.x += v.x; a.y += v.y; a.z += v.z; a.w += v.w;
    }
    ((float4*)out)[i4] = a;
}

// ===========================================================================
// Launcher
// ===========================================================================
extern "C" void kernel_launch(void* const* d_in, const int* in_sizes, int n_in,
                              void* d_out, int out_size)
{
    const float* x      = (const float*)d_in[0];
    const float* mw1    = (const float*)d_in[1];
    const float* mb1    = (const float*)d_in[2];
    const float* mw2    = (const float*)d_in[3];
    const float* mb2    = (const float*)d_in[4];
    const float* mlw    = (const float*)d_in[5];
    const float* mlb    = (const float*)d_in[6];
    const float* mgw    = (const float*)d_in[7];
    const float* mgb    = (const float*)d_in[8];
    const float* mlw2   = (const float*)d_in[9];
    const float* mlb2   = (const float*)d_in[10];
    const float* mgamma = (const float*)d_in[11];
    const float* mbeta  = (const float*)d_in[12];
    const float* w1     = (const float*)d_in[13];
    const float* b1     = (const float*)d_in[14];
    const float* w2     = (const float*)d_in[15];
    const float* b2     = (const float*)d_in[16];
    const float* gw     = (const float*)d_in[17];
    const float* gb     = (const float*)d_in[18];
    const float* lw     = (const float*)d_in[19];
    const float* lb     = (const float*)d_in[20];
    const float* gamma  = (const float*)d_in[21];
    const float* beta   = (const float*)d_in[22];

    float* out = (float*)d_out;
    float* out_mask = ((long long)out_size >= (long long)B_ * (64 + 32))
                          ? out + (size_t)B_ * 64 : nullptr;

    static const size_t k1_smem = K1_SMEM_FLOATS * sizeof(float);
    static const size_t k2_smem = K2_SMEM_FLOATS * sizeof(float);
    cudaFuncSetAttribute(k1_mask_kernel, cudaFuncAttributeMaxDynamicSharedMemorySize, (int)k1_smem);
    cudaFuncSetAttribute(k2_grn_kernel,  cudaFuncAttributeMaxDynamicSharedMemorySize, (int)k2_smem);

    float* gmask_ptr = nullptr;
    float* vbuf_ptr  = nullptr;
    cudaGetSymbolAddress((void**)&gmask_ptr, g_mask_buf);
    cudaGetSymbolAddress((void**)&vbuf_ptr,  g_vbuf);

    k1_mask_kernel<<<B_ / BM, 128, k1_smem>>>(x, mw1, mb1, mw2, mb2, mlw, mlb,
                                              mgw, mgb, mlw2, mlb2, mgamma, mbeta,
                                              gmask_ptr, out_mask);
    k2_grn_kernel<<<F_ * (B_ / R2), T2, k2_smem>>>(x, w1, b1, w2, b2,
                                                   gw, gb, lw, lb, gamma, beta,
                                                   gmask_ptr, vbuf_ptr);
    k3_reduce_kernel<<<(B_ * D_ / 4) / K3_T, K3_T>>>(vbuf_ptr, out);
}

// round 5
// speedup vs baseline: 1.8983x; 1.8983x over previous
#include <cuda_runtime.h>
#include <cuda_bf16.h>
#include <cuda_fp16.h>
#include <math.h>
#include <stdint.h>

// Problem constants
#define B_  16384
#define F_  32
#define D_  64
#define IN_ 2048   // F_*D_
#define EPS_ 1e-5f

// ---------------------------------------------------------------------------
// Scratch (no device mallocs allowed)
// ---------------------------------------------------------------------------
__device__ float g_mask_buf[(size_t)B_ * F_];
__device__ float g_vbuf[(size_t)F_ * B_ * D_];

// ---------------------------------------------------------------------------
// helpers
// ---------------------------------------------------------------------------
__device__ __forceinline__ uint32_t smem_u32(const void* p) {
    uint32_t a;
    asm("{ .reg .u64 t; cvta.to.shared.u64 t, %1; cvt.u32.u64 %0, t; }" : "=r"(a) : "l"(p));
    return a;
}
__device__ __forceinline__ void ldsm4(uint32_t* r, uint32_t a) {
    asm volatile("ldmatrix.sync.aligned.m8n8.x4.shared.b16 {%0,%1,%2,%3}, [%4];"
        : "=r"(r[0]), "=r"(r[1]), "=r"(r[2]), "=r"(r[3]) : "r"(a));
}
__device__ __forceinline__ void mma16816(float* d, const uint32_t* a, const uint32_t* b) {
    asm volatile("mma.sync.aligned.m16n8k16.row.col.f32.f16.f16.f32 "
        "{%0,%1,%2,%3},{%4,%5,%6,%7},{%8,%9},{%0,%1,%2,%3};"
        : "+f"(d[0]), "+f"(d[1]), "+f"(d[2]), "+f"(d[3])
        : "r"(a[0]), "r"(a[1]), "r"(a[2]), "r"(a[3]), "r"(b[0]), "r"(b[1]));
}
__device__ __forceinline__ uint32_t packh(__half a, __half b) {
    __half2 t = __halves2half2(a, b);
    return *(uint32_t*)&t;
}
__device__ __forceinline__ void split16(float v, __half& h, __half& l) {
    h = __float2half_rn(v);
    l = __float2half_rn(v - __half2float(h));
}

typedef unsigned long long u64;
__device__ __forceinline__ u64 pk2(float v) {
    u64 r; asm("mov.b64 %0,{%1,%1};" : "=l"(r) : "f"(v)); return r;
}
__device__ __forceinline__ void fma2(u64& d, u64 a, u64 b) {
    asm("fma.rn.f32x2 %0,%1,%2,%0;" : "+l"(d) : "l"(a), "l"(b));
}
__device__ __forceinline__ float2 up2(u64 v) {
    float2 f; asm("mov.b64 {%0,%1},%2;" : "=f"(f.x), "=f"(f.y) : "l"(v)); return f;
}

// ===========================================================================
// Kernel 1: mask branch (R3 version — 215us measured). BM=64, 128 thr.
// ===========================================================================
#define BM 64
#define BK 32
#define AS_STRIDE 36
#define BS_STRIDE 100
#define CS_STRIDE 97
#define K1_SMEM_FLOATS (BM*AS_STRIDE + BK*BS_STRIDE + BM*CS_STRIDE + 2048 + 1024 + 1024 + 256)

__global__ __launch_bounds__(128, 3)
void k1_mask_kernel(const float* __restrict__ x,
                    const float* __restrict__ mw1, const float* __restrict__ mb1,
                    const float* __restrict__ mw2, const float* __restrict__ mb2,
                    const float* __restrict__ mlw, const float* __restrict__ mlb,
                    const float* __restrict__ mgw, const float* __restrict__ mgb,
                    const float* __restrict__ mlw2, const float* __restrict__ mlb2,
                    const float* __restrict__ mgamma, const float* __restrict__ mbeta,
                    float* __restrict__ gmask, float* __restrict__ out_mask)
{
    extern __shared__ float sm[];
    float* As    = sm;
    float* Bs    = As  + BM * AS_STRIDE;
    float* Cs    = Bs  + BK * BS_STRIDE;
    float* mw2s  = Cs  + BM * CS_STRIDE;
    float* mgws  = mw2s + 2048;
    float* mlw2s = mgws + 1024;
    float* mb1s  = mlw2s + 1024;
    float* mb2s  = mb1s + 64;
    float* mgbs  = mb2s + 32;
    float* mlb2s = mgbs + 32;
    float* mlbs  = mlb2s + 32;
    float* mgammas = mlbs + 32;
    float* mbetas  = mgammas + 32;

    const int tid = threadIdx.x;
    const int ty  = tid >> 4;
    const int tx  = tid & 15;
    const int m0  = blockIdx.x * BM;

    for (int i = tid; i < 2048; i += 128) mw2s[i] = mw2[i];
    for (int i = tid; i < 1024; i += 128) { mgws[i] = mgw[i]; mlw2s[i] = mlw2[i]; }
    if (tid < 64) mb1s[tid] = mb1[tid];
    if (tid < 32) {
        mb2s[tid]  = mb2[tid];  mgbs[tid] = mgb[tid];  mlb2s[tid] = mlb2[tid];
        mlbs[tid]  = mlb[tid];  mgammas[tid] = mgamma[tid]; mbetas[tid] = mbeta[tid];
    }

    u64 c2[8][3];
#pragma unroll
    for (int i = 0; i < 8; i++)
#pragma unroll
        for (int j = 0; j < 3; j++) c2[i][j] = 0ull;

    const int ar  = tid >> 3;
    const int ac  = (tid & 7) * 4;
    const int br  = tid >> 2;
    const int bq  = tid & 3;

    for (int k0 = 0; k0 < IN_; k0 += BK) {
        __syncthreads();
#pragma unroll
        for (int p = 0; p < 4; p++) {
            int m = ar + 16 * p;
            float4 v = *(const float4*)&x[(size_t)(m0 + m) * IN_ + k0 + ac];
            *(float4*)&As[m * AS_STRIDE + ac] = v;
        }
#pragma unroll
        for (int q = 0; q < 6; q++) {
            int c4  = bq * 6 + q;
            int col = c4 * 4;
            float4 v;
            if (col < 64) v = *(const float4*)&mw1[(size_t)(k0 + br) * 64 + col];
            else          v = *(const float4*)&mlw[(size_t)(k0 + br) * 32 + (col - 64)];
            *(float4*)&Bs[br * BS_STRIDE + col] = v;
        }
        __syncthreads();

#pragma unroll
        for (int k = 0; k < BK; k++) {
            u64 b0 = *(const u64*)&Bs[k * BS_STRIDE + tx * 6];
            u64 b1 = *(const u64*)&Bs[k * BS_STRIDE + tx * 6 + 2];
            u64 b2 = *(const u64*)&Bs[k * BS_STRIDE + tx * 6 + 4];
#pragma unroll
            for (int i = 0; i < 8; i++) {
                u64 ap = pk2(As[(ty * 8 + i) * AS_STRIDE + k]);
                fma2(c2[i][0], ap, b0);
                fma2(c2[i][1], ap, b1);
                fma2(c2[i][2], ap, b2);
            }
        }
    }
    __syncthreads();
#pragma unroll
    for (int i = 0; i < 8; i++) {
        float* dst = &Cs[(ty * 8 + i) * CS_STRIDE + tx * 6];
        float2 v0 = up2(c2[i][0]), v1 = up2(c2[i][1]), v2 = up2(c2[i][2]);
        dst[0] = v0.x; dst[1] = v0.y; dst[2] = v1.x;
        dst[3] = v1.y; dst[4] = v2.x; dst[5] = v2.y;
    }
    __syncthreads();

    if (tid < BM) {
        const int base = tid * CS_STRIDE;
        const size_t gr = (size_t)(m0 + tid);

#pragma unroll 4
        for (int e = 0; e < 64; e++) {
            float v = Cs[base + e] + mb1s[e];
            Cs[base + e] = v > 0.f ? v : (__expf(v) - 1.0f);
        }
        float h[32];
#pragma unroll
        for (int j = 0; j < 32; j++) h[j] = mb2s[j];
#pragma unroll 4
        for (int e = 0; e < 64; e++) {
            float ev = Cs[base + e];
#pragma unroll
            for (int j = 0; j < 32; j++) h[j] = fmaf(ev, mw2s[e * 32 + j], h[j]);
        }
#pragma unroll
        for (int j = 0; j < 32; j++) Cs[base + j] = h[j];

        float g[32], l[32];
#pragma unroll
        for (int j = 0; j < 32; j++) { g[j] = mgbs[j]; l[j] = mlb2s[j]; }
#pragma unroll 2
        for (int i = 0; i < 32; i++) {
            float hv = Cs[base + i];
#pragma unroll
            for (int j = 0; j < 32; j++) {
                g[j] = fmaf(hv, mgws[i * 32 + j], g[j]);
                l[j] = fmaf(hv, mlw2s[i * 32 + j], l[j]);
            }
        }
        float pre[32];
#pragma unroll
        for (int j = 0; j < 32; j++) {
            float sig = 1.f / (1.f + __expf(-g[j]));
            pre[j] = fmaf(sig, l[j], Cs[base + 64 + j] + mlbs[j]);
        }
        float mean = 0.f;
#pragma unroll
        for (int j = 0; j < 32; j++) mean += pre[j];
        mean *= (1.f / 32.f);
        float var = 0.f;
#pragma unroll
        for (int j = 0; j < 32; j++) { float d = pre[j] - mean; var = fmaf(d, d, var); }
        var *= (1.f / 32.f);
        float inv = rsqrtf(var + EPS_);
        float mx = -3.4e38f;
#pragma unroll
        for (int j = 0; j < 32; j++) {
            pre[j] = fmaf((pre[j] - mean) * inv, mgammas[j], mbetas[j]);
            mx = fmaxf(mx, pre[j]);
        }
        float ssum = 0.f;
#pragma unroll
        for (int j = 0; j < 32; j++) { pre[j] = __expf(pre[j] - mx); ssum += pre[j]; }
        float rinv = 1.f / ssum;
#pragma unroll
        for (int j = 0; j < 32; j++) {
            float mv = pre[j] * rinv;
            gmask[gr * 32 + j] = mv;
            if (out_mask) out_mask[gr * 32 + j] = mv;
        }
    }
}

// ===========================================================================
// Kernel 2: split-fp16 mma.sync GRN chain. 128 rows x 1 feature per CTA,
// 128 threads (4 warps, warp = 32 rows x 64 cols).
// ===========================================================================
// smem byte map
#define SM_BIAS   0        // 6*64 f32 = 1536
#define SM_MSK    1536     // 128 f32  = 512
#define SM_ACTH   2048     // 128x72 f16 = 18432
#define SM_ACTL   20480    // 18432
#define SM_W0H    38912    // 64x72 f16 = 9216
#define SM_W0L    48128
#define SM_W1H    57344
#define SM_W1L    66560
#define SM_TOTAL  75776
#define ASTR_B    144      // act row stride bytes (72 halfs)
#define WSTR_B    144      // wt row stride bytes

// full-n GEMM pass: acc[nt][mt][i] += 3-pass split-fp16 A@W
__device__ __forceinline__ void gemm_full(uint32_t actH, uint32_t actL,
                                          uint32_t wtH, uint32_t wtL,
                                          uint32_t aIdx, uint32_t bIdx,
                                          float acc[8][2][4])
{
#pragma unroll
    for (int kt = 0; kt < 4; kt++) {
        uint32_t ah[2][4], al[2][4];
#pragma unroll
        for (int mt = 0; mt < 2; mt++) {
            ldsm4(ah[mt], actH + aIdx + mt * 2304 + kt * 32);
            ldsm4(al[mt], actL + aIdx + mt * 2304 + kt * 32);
        }
        uint32_t bh[8][2], bl[8][2];
#pragma unroll
        for (int p = 0; p < 4; p++) {
            ldsm4(&bh[p * 2][0], wtH + bIdx + p * 2304 + kt * 32);
            ldsm4(&bl[p * 2][0], wtL + bIdx + p * 2304 + kt * 32);
        }
#pragma unroll
        for (int nt = 0; nt < 8; nt++)
#pragma unroll
            for (int mt = 0; mt < 2; mt++) {
                mma16816(acc[nt][mt], ah[mt], bh[nt]);
                mma16816(acc[nt][mt], ah[mt], bl[nt]);
                mma16816(acc[nt][mt], al[mt], bh[nt]);
            }
    }
}

// half-n fused gate+lin pass (n-tiles h*4 .. h*4+3)
__device__ __forceinline__ void gemm_half(uint32_t actH, uint32_t actL,
                                          uint32_t gH, uint32_t gL,
                                          uint32_t lH, uint32_t lL,
                                          uint32_t aIdx, uint32_t bIdx, int h,
                                          float accg[4][2][4], float accl[4][2][4])
{
#pragma unroll
    for (int kt = 0; kt < 4; kt++) {
        uint32_t ah[2][4], al[2][4];
#pragma unroll
        for (int mt = 0; mt < 2; mt++) {
            ldsm4(ah[mt], actH + aIdx + mt * 2304 + kt * 32);
            ldsm4(al[mt], actL + aIdx + mt * 2304 + kt * 32);
        }
        uint32_t bgh[4][2], bgl[4][2], blh[4][2], bll[4][2];
#pragma unroll
        for (int q = 0; q < 2; q++) {
            int p = h * 2 + q;
            ldsm4(&bgh[q * 2][0], gH + bIdx + p * 2304 + kt * 32);
            ldsm4(&bgl[q * 2][0], gL + bIdx + p * 2304 + kt * 32);
            ldsm4(&blh[q * 2][0], lH + bIdx + p * 2304 + kt * 32);
            ldsm4(&bll[q * 2][0], lL + bIdx + p * 2304 + kt * 32);
        }
#pragma unroll
        for (int nt = 0; nt < 4; nt++)
#pragma unroll
            for (int mt = 0; mt < 2; mt++) {
                mma16816(accg[nt][mt], ah[mt], bgh[nt]);
                mma16816(accg[nt][mt], ah[mt], bgl[nt]);
                mma16816(accg[nt][mt], al[mt], bgh[nt]);
                mma16816(accl[nt][mt], ah[mt], blh[nt]);
                mma16816(accl[nt][mt], ah[mt], bll[nt]);
                mma16816(accl[nt][mt], al[mt], blh[nt]);
            }
    }
}

// stage a 64x64 weight matrix: split fp16 hi/lo, transposed Wt[e][d]
__device__ __forceinline__ void stage_wt(const float* __restrict__ W,
                                         char* dstH, char* dstL, int tid)
{
#pragma unroll
    for (int i = 0; i < 32; i++) {
        int idx = tid + 128 * i;
        int d = idx >> 6, e = idx & 63;
        __half hh, hl;
        split16(W[idx], hh, hl);
        *(__half*)(dstH + (e * 72 + d) * 2) = hh;
        *(__half*)(dstL + (e * 72 + d) * 2) = hl;
    }
}

__global__ __launch_bounds__(128, 2)
void k2_grn_mma(const float* __restrict__ x,
                const float* __restrict__ w1, const float* __restrict__ b1,
                const float* __restrict__ w2, const float* __restrict__ b2,
                const float* __restrict__ gw, const float* __restrict__ gb,
                const float* __restrict__ lw, const float* __restrict__ lb,
                const float* __restrict__ gamma, const float* __restrict__ beta,
                const float* __restrict__ gmask, float* __restrict__ vbuf)
{
    extern __shared__ char smc[];
    const uint32_t smb = smem_u32(smc);
    float* bias = (float*)(smc + SM_BIAS);
    float* msk  = (float*)(smc + SM_MSK);

    const int tid  = threadIdx.x;
    const int lane = tid & 31;
    const int w    = tid >> 5;
    const int f    = blockIdx.x >> 7;
    const int r0c  = (blockIdx.x & 127) * 128;
    const size_t wo = (size_t)f * 4096;

    const uint32_t actH = smb + SM_ACTH, actL = smb + SM_ACTL;
    const uint32_t w0H  = smb + SM_W0H,  w0L  = smb + SM_W0L;
    const uint32_t w1H  = smb + SM_W1H,  w1L  = smb + SM_W1L;

    // per-lane ldmatrix index bases (bytes)
    const uint32_t aIdx = ((uint32_t)(w * 32 + (lane & 15)) * 72 + (uint32_t)(lane >> 4) * 8) * 2;
    const uint32_t bIdx = ((uint32_t)((lane & 7) + ((lane >> 4) & 1) * 8)) * WSTR_B
                        + ((uint32_t)((lane >> 3) & 1)) * 16;

    // ---- initial staging ----
    // biases
    if (tid < 64) {
        bias[tid]         = b1[f * 64 + tid];
        bias[64 + tid]    = b2[f * 64 + tid];
        bias[128 + tid]   = gb[f * 64 + tid];
        bias[192 + tid]   = lb[f * 64 + tid];
        bias[256 + tid]   = gamma[f * 64 + tid];
        bias[320 + tid]   = beta[f * 64 + tid];
    }
    msk[tid] = gmask[(size_t)(r0c + tid) * F_ + f];
    // act = split(x)
#pragma unroll
    for (int q = 0; q < 16; q++) {
        int j   = tid + 128 * q;       // float4 index
        int row = j >> 4;
        int seg = j & 15;
        float4 v = *(const float4*)&x[((size_t)(r0c + row) * F_ + f) * 64 + seg * 4];
        __half h0, l0, h1, l1, h2, l2, h3, l3;
        split16(v.x, h0, l0); split16(v.y, h1, l1);
        split16(v.z, h2, l2); split16(v.w, h3, l3);
        *(uint32_t*)(smc + SM_ACTH + row * ASTR_B + seg * 8)     = packh(h0, h1);
        *(uint32_t*)(smc + SM_ACTH + row * ASTR_B + seg * 8 + 4) = packh(h2, h3);
        *(uint32_t*)(smc + SM_ACTL + row * ASTR_B + seg * 8)     = packh(l0, l1);
        *(uint32_t*)(smc + SM_ACTL + row * ASTR_B + seg * 8 + 4) = packh(l2, l3);
    }
    // weights: w1 -> buf0, w2 -> buf1
    stage_wt(w1 + wo, smc + SM_W0H, smc + SM_W0L, tid);
    stage_wt(w2 + wo, smc + SM_W1H, smc + SM_W1L, tid);
    __syncthreads();

    const int gid = lane >> 2, tc = lane & 3;

    // ================= stage 1: hh1 = elu(x @ w1 + b1) =================
    {
        float acc[8][2][4];
#pragma unroll
        for (int nt = 0; nt < 8; nt++)
#pragma unroll
            for (int mt = 0; mt < 2; mt++)
#pragma unroll
                for (int i = 0; i < 4; i++) acc[nt][mt][i] = 0.f;
        gemm_full(actH, actL, w0H, w0L, aIdx, bIdx, acc);
        __syncthreads();   // everyone done reading act + buf0
        // epilogue: +b1, ELU, split, write act
#pragma unroll
        for (int nt = 0; nt < 8; nt++) {
            int c = nt * 8 + tc * 2;
            float bb0 = bias[c], bb1 = bias[c + 1];
#pragma unroll
            for (int mt = 0; mt < 2; mt++) {
                int r0 = w * 32 + mt * 16 + gid;
#pragma unroll
                for (int jj = 0; jj < 2; jj++) {
                    int row = r0 + jj * 8;
                    float v0 = acc[nt][mt][jj * 2]     + bb0;
                    float v1 = acc[nt][mt][jj * 2 + 1] + bb1;
                    v0 = v0 > 0.f ? v0 : (__expf(v0) - 1.f);
                    v1 = v1 > 0.f ? v1 : (__expf(v1) - 1.f);
                    __half h0, l0, h1, l1;
                    split16(v0, h0, l0); split16(v1, h1, l1);
                    *(uint32_t*)(smc + SM_ACTH + row * ASTR_B + c * 2) = packh(h0, h1);
                    *(uint32_t*)(smc + SM_ACTL + row * ASTR_B + c * 2) = packh(l0, l1);
                }
            }
        }
        // restage gw -> buf0 (buf0 free now)
        stage_wt(gw + wo, smc + SM_W0H, smc + SM_W0L, tid);
    }
    __syncthreads();

    // ================= stage 2: hh2 = hh1 @ w2 + b2 =================
    {
        float acc[8][2][4];
#pragma unroll
        for (int nt = 0; nt < 8; nt++)
#pragma unroll
            for (int mt = 0; mt < 2; mt++)
#pragma unroll
                for (int i = 0; i < 4; i++) acc[nt][mt][i] = 0.f;
        gemm_full(actH, actL, w1H, w1L, aIdx, bIdx, acc);
        __syncthreads();   // done reading act + buf1
#pragma unroll
        for (int nt = 0; nt < 8; nt++) {
            int c = nt * 8 + tc * 2;
            float bb0 = bias[64 + c], bb1 = bias[64 + c + 1];
#pragma unroll
            for (int mt = 0; mt < 2; mt++) {
                int r0 = w * 32 + mt * 16 + gid;
#pragma unroll
                for (int jj = 0; jj < 2; jj++) {
                    int row = r0 + jj * 8;
                    float v0 = acc[nt][mt][jj * 2]     + bb0;
                    float v1 = acc[nt][mt][jj * 2 + 1] + bb1;
                    __half h0, l0, h1, l1;
                    split16(v0, h0, l0); split16(v1, h1, l1);
                    *(uint32_t*)(smc + SM_ACTH + row * ASTR_B + c * 2) = packh(h0, h1);
                    *(uint32_t*)(smc + SM_ACTL + row * ASTR_B + c * 2) = packh(l0, l1);
                }
            }
        }
        // restage lw -> buf1
        stage_wt(lw + wo, smc + SM_W1H, smc + SM_W1L, tid);
    }
    __syncthreads();

    // ============ stage 3+4 fused, two n-halves; y + layernorm ============
    {
        float y[2][8][4];
        float s1[2][2] = {{0.f, 0.f}, {0.f, 0.f}};
        float s2[2][2] = {{0.f, 0.f}, {0.f, 0.f}};

#pragma unroll
        for (int h = 0; h < 2; h++) {
            float accg[4][2][4], accl[4][2][4];
#pragma unroll
            for (int nt = 0; nt < 4; nt++)
#pragma unroll
                for (int mt = 0; mt < 2; mt++)
#pragma unroll
                    for (int i = 0; i < 4; i++) { accg[nt][mt][i] = 0.f; accl[nt][mt][i] = 0.f; }
            gemm_half(actH, actL, w0H, w0L, w1H, w1L, aIdx, bIdx, h, accg, accl);
            // y = sigmoid(ga+gb)*(la+lb) + x
#pragma unroll
            for (int nt = 0; nt < 4; nt++) {
                int c = (h * 4 + nt) * 8 + tc * 2;
                float gb0 = bias[128 + c], gb1 = bias[128 + c + 1];
                float lb0 = bias[192 + c], lb1 = bias[192 + c + 1];
#pragma unroll
                for (int mt = 0; mt < 2; mt++) {
                    int r0 = w * 32 + mt * 16 + gid;
#pragma unroll
                    for (int jj = 0; jj < 2; jj++) {
                        int row = r0 + jj * 8;
                        const float2 xv = *(const float2*)&x[((size_t)(r0c + row) * F_ + f) * 64 + c];
                        float ga0 = accg[nt][mt][jj * 2]     + gb0;
                        float ga1 = accg[nt][mt][jj * 2 + 1] + gb1;
                        float la0 = accl[nt][mt][jj * 2]     + lb0;
                        float la1 = accl[nt][mt][jj * 2 + 1] + lb1;
                        float sg0 = 1.f / (1.f + __expf(-ga0));
                        float sg1 = 1.f / (1.f + __expf(-ga1));
                        float y0 = fmaf(sg0, la0, xv.x);
                        float y1 = fmaf(sg1, la1, xv.y);
                        y[mt][h * 4 + nt][jj * 2]     = y0;
                        y[mt][h * 4 + nt][jj * 2 + 1] = y1;
                        s1[mt][jj] += y0 + y1;
                        s2[mt][jj] = fmaf(y0, y0, fmaf(y1, y1, s2[mt][jj]));
                    }
                }
            }
        }

        // row reductions across the tc quad (lanes gid*4 .. gid*4+3)
#pragma unroll
        for (int mt = 0; mt < 2; mt++)
#pragma unroll
            for (int jj = 0; jj < 2; jj++) {
#pragma unroll
                for (int o = 1; o < 4; o <<= 1) {
                    s1[mt][jj] += __shfl_xor_sync(0xFFFFFFFFu, s1[mt][jj], o);
                    s2[mt][jj] += __shfl_xor_sync(0xFFFFFFFFu, s2[mt][jj], o);
                }
            }

        // normalize + mask + store
#pragma unroll
        for (int mt = 0; mt < 2; mt++) {
            int r0 = w * 32 + mt * 16 + gid;
#pragma unroll
            for (int jj = 0; jj < 2; jj++) {
                int row = r0 + jj * 8;
                float mean = s1[mt][jj] * (1.f / 64.f);
                float var  = fmaf(-mean, mean, s2[mt][jj] * (1.f / 64.f));
                float inv  = rsqrtf(var + EPS_);
                float mv   = msk[row];
                float* dstrow = &vbuf[((size_t)f * B_ + (size_t)(r0c + row)) * 64];
#pragma unroll
                for (int nt = 0; nt < 8; nt++) {
                    int c = nt * 8 + tc * 2;
                    float gm0 = bias[256 + c], gm1 = bias[256 + c + 1];
                    float bt0 = bias[320 + c], bt1 = bias[320 + c + 1];
                    float o0 = mv * fmaf((y[mt][nt][jj * 2]     - mean) * inv, gm0, bt0);
                    float o1 = mv * fmaf((y[mt][nt][jj * 2 + 1] - mean) * inv, gm1, bt1);
                    *(float2*)&dstrow[c] = make_float2(o0, o1);
                }
            }
        }
    }
}

// ===========================================================================
// Kernel 3: out[b,d] = sum_f vbuf[f,b,d]. Pure bandwidth (~268MB).
// ===========================================================================
#define K3_T 256
__global__ __launch_bounds__(K3_T, 4)
void k3_reduce_kernel(const float* __restrict__ vbuf, float* __restrict__ out)
{
    const size_t i4 = (size_t)blockIdx.x * K3_T + threadIdx.x;
    const size_t stride4 = (size_t)B_ * D_ / 4;
    const float4* vb = (const float4*)vbuf;
    float4 a = vb[i4];
#pragma unroll 4
    for (int f = 1; f < F_; f++) {
        float4 v = vb[i4 + (size_t)f * stride4];
        a.x += v.x; a.y += v.y; a.z += v.z; a.w += v.w;
    }
    ((float4*)out)[i4] = a;
}

// ===========================================================================
// Launcher
// ===========================================================================
extern "C" void kernel_launch(void* const* d_in, const int* in_sizes, int n_in,
                              void* d_out, int out_size)
{
    const float* x      = (const float*)d_in[0];
    const float* mw1    = (const float*)d_in[1];
    const float* mb1    = (const float*)d_in[2];
    const float* mw2    = (const float*)d_in[3];
    const float* mb2    = (const float*)d_in[4];
    const float* mlw    = (const float*)d_in[5];
    const float* mlb    = (const float*)d_in[6];
    const float* mgw    = (const float*)d_in[7];
    const float* mgb    = (const float*)d_in[8];
    const float* mlw2   = (const float*)d_in[9];
    const float* mlb2   = (const float*)d_in[10];
    const float* mgamma = (const float*)d_in[11];
    const float* mbeta  = (const float*)d_in[12];
    const float* w1     = (const float*)d_in[13];
    const float* b1     = (const float*)d_in[14];
    const float* w2     = (const float*)d_in[15];
    const float* b2     = (const float*)d_in[16];
    const float* gw     = (const float*)d_in[17];
    const float* gb     = (const float*)d_in[18];
    const float* lw     = (const float*)d_in[19];
    const float* lb     = (const float*)d_in[20];
    const float* gamma  = (const float*)d_in[21];
    const float* beta   = (const float*)d_in[22];

    float* out = (float*)d_out;
    float* out_mask = ((long long)out_size >= (long long)B_ * (64 + 32))
                          ? out + (size_t)B_ * 64 : nullptr;

    static const size_t k1_smem = K1_SMEM_FLOATS * sizeof(float);
    cudaFuncSetAttribute(k1_mask_kernel, cudaFuncAttributeMaxDynamicSharedMemorySize, (int)k1_smem);
    cudaFuncSetAttribute(k2_grn_mma, cudaFuncAttributeMaxDynamicSharedMemorySize, SM_TOTAL);

    float* gmask_ptr = nullptr;
    float* vbuf_ptr  = nullptr;
    cudaGetSymbolAddress((void**)&gmask_ptr, g_mask_buf);
    cudaGetSymbolAddress((void**)&vbuf_ptr,  g_vbuf);

    k1_mask_kernel<<<B_ / BM, 128, k1_smem>>>(x, mw1, mb1, mw2, mb2, mlw, mlb,
                                              mgw, mgb, mlw2, mlb2, mgamma, mbeta,
                                              gmask_ptr, out_mask);
    k2_grn_mma<<<F_ * (B_ / 128), 128, SM_TOTAL>>>(x, w1, b1, w2, b2,
                                                   gw, gb, lw, lb, gamma, beta,
                                                   gmask_ptr, vbuf_ptr);
    k3_reduce_kernel<<<(B_ * D_ / 4) / K3_T, K3_T>>>(vbuf_ptr, out);
}

// round 6
// speedup vs baseline: 2.7418x; 1.4444x over previous
#include <cuda_runtime.h>
#include <cuda_bf16.h>
#include <cuda_fp16.h>
#include <math.h>
#include <stdint.h>

// Problem constants
#define B_  16384
#define F_  32
#define D_  64
#define IN_ 2048   // F_*D_
#define EPS_ 1e-5f

// ---------------------------------------------------------------------------
// Scratch (no device mallocs allowed)
// ---------------------------------------------------------------------------
__device__ float g_mask_buf[(size_t)B_ * F_];
__device__ float g_vbuf[(size_t)F_ * B_ * D_];
// k1 weights, split fp16, transposed [n=96][k=2048]
__device__ __align__(16) __half g_k1bh[96 * IN_];
__device__ __align__(16) __half g_k1bl[96 * IN_];
// k2 weights: per (f, matrix m in {w1,w2,gw,lw}, hi/lo) a 64x72-half smem image
#define K2IMG 4608   // 64*72 halfs
__device__ __align__(16) __half g_k2w[(size_t)F_ * 4 * 2 * K2IMG];

// ---------------------------------------------------------------------------
// helpers
// ---------------------------------------------------------------------------
__device__ __forceinline__ uint32_t smem_u32(const void* p) {
    uint32_t a;
    asm("{ .reg .u64 t; cvta.to.shared.u64 t, %1; cvt.u32.u64 %0, t; }" : "=r"(a) : "l"(p));
    return a;
}
__device__ __forceinline__ void ldsm4(uint32_t* r, uint32_t a) {
    asm volatile("ldmatrix.sync.aligned.m8n8.x4.shared.b16 {%0,%1,%2,%3}, [%4];"
        : "=r"(r[0]), "=r"(r[1]), "=r"(r[2]), "=r"(r[3]) : "r"(a));
}
__device__ __forceinline__ void mma16816(float* d, const uint32_t* a, const uint32_t* b) {
    asm volatile("mma.sync.aligned.m16n8k16.row.col.f32.f16.f16.f32 "
        "{%0,%1,%2,%3},{%4,%5,%6,%7},{%8,%9},{%0,%1,%2,%3};"
        : "+f"(d[0]), "+f"(d[1]), "+f"(d[2]), "+f"(d[3])
        : "r"(a[0]), "r"(a[1]), "r"(a[2]), "r"(a[3]), "r"(b[0]), "r"(b[1]));
}
__device__ __forceinline__ uint32_t packh(__half a, __half b) {
    __half2 t = __halves2half2(a, b);
    return *(uint32_t*)&t;
}
__device__ __forceinline__ void split16(float v, __half& h, __half& l) {
    h = __float2half_rn(v);
    l = __float2half_rn(v - __half2float(h));
}

// ===========================================================================
// Kernel 0a: split k1 weights into g_k1bh/g_k1bl, transposed [n][k].
// ===========================================================================
__global__ void k0a_split_k1w(const float* __restrict__ mw1,
                              const float* __restrict__ mlw)
{
    int idx = blockIdx.x * 256 + threadIdx.x;      // 96*2048 total
    if (idx >= 96 * IN_) return;
    int n = idx >> 11, k = idx & (IN_ - 1);
    float v = (n < 64) ? mw1[(size_t)k * 64 + n] : mlw[(size_t)k * 32 + (n - 64)];
    __half h, l; split16(v, h, l);
    g_k1bh[idx] = h;
    g_k1bl[idx] = l;
}

// ===========================================================================
// Kernel 0b: split k2 weights into ready 64x72-half smem images (hi/lo).
// ===========================================================================
__global__ void k0b_split_k2w(const float* __restrict__ w1, const float* __restrict__ w2,
                              const float* __restrict__ gw, const float* __restrict__ lw)
{
    int idx = blockIdx.x * 256 + threadIdx.x;      // 32*4*4096 total
    if (idx >= F_ * 4 * 4096) return;
    int f = idx >> 14, m = (idx >> 12) & 3, e = (idx >> 6) & 63, d = idx & 63;
    const float* W = (m == 0) ? w1 : (m == 1) ? w2 : (m == 2) ? gw : lw;
    float v = W[(size_t)f * 4096 + d * 64 + e];
    __half h, l; split16(v, h, l);
    size_t base = ((size_t)(f * 4 + m)) * 2 * K2IMG;
    g_k2w[base + e * 72 + d] = h;
    g_k2w[base + K2IMG + e * 72 + d] = l;
}

// ===========================================================================
// Kernel 1 (tensor): mask branch. BM=64 rows/CTA, 128 threads, 256 CTAs.
// C[64,96] = x_tile @ [mw1|mlw] via split-fp16 mma.sync (3 passes), then the
// scalar per-row epilogue (elu->mlp->gate->layernorm->softmax).
// ===========================================================================
// smem byte map (tiles aliased by Cs after mainloop)
#define S1_AH   0         // 64x72 f16 = 9216
#define S1_AL   9216
#define S1_BH   18432     // 96x72 f16 = 13824
#define S1_BL   32256
#define S1_TILE_END 46080
#define S1_EPI  46080     // mw2s f32[2048]
#define S1_MGW  (S1_EPI + 8192)     // f32[1024]
#define S1_MLW2 (S1_MGW + 4096)    // f32[1024]
#define S1_BIAS (S1_MLW2 + 4096)   // 256 f32
#define S1_TOTAL (S1_BIAS + 1024)  // 63488
#define K1_CHUNKS (IN_ / 64)

__global__ __launch_bounds__(128, 2)
void k1_mask_mma(const float* __restrict__ x,
                 const float* __restrict__ mb1,
                 const float* __restrict__ mw2, const float* __restrict__ mb2,
                 const float* __restrict__ mlb,
                 const float* __restrict__ mgw, const float* __restrict__ mgb,
                 const float* __restrict__ mlw2, const float* __restrict__ mlb2,
                 const float* __restrict__ mgamma, const float* __restrict__ mbeta,
                 float* __restrict__ gmask, float* __restrict__ out_mask)
{
    extern __shared__ char smc[];
    const uint32_t smb = smem_u32(smc);
    float* Cs    = (float*)smc;               // alias over tiles, stride 97
    float* mw2s  = (float*)(smc + S1_EPI);
    float* mgws  = (float*)(smc + S1_MGW);
    float* mlw2s = (float*)(smc + S1_MLW2);
    float* bias  = (float*)(smc + S1_BIAS);   // mb1[64] mb2 mgb mlb2 mlb mgamma mbeta

    const int tid  = threadIdx.x;
    const int lane = tid & 31;
    const int w    = tid >> 5;
    const int m0   = blockIdx.x * 64;

    // stage epilogue weights
    for (int i = tid; i < 2048; i += 128) mw2s[i] = mw2[i];
    for (int i = tid; i < 1024; i += 128) { mgws[i] = mgw[i]; mlw2s[i] = mlw2[i]; }
    if (tid < 64) bias[tid] = mb1[tid];
    if (tid < 32) {
        bias[64 + tid]  = mb2[tid];   bias[96 + tid]  = mgb[tid];
        bias[128 + tid] = mlb2[tid];  bias[160 + tid] = mlb[tid];
        bias[192 + tid] = mgamma[tid]; bias[224 + tid] = mbeta[tid];
    }

    const uint32_t aIdx = (uint32_t)(w * 16 + (lane & 15)) * 144 + (uint32_t)(lane >> 4) * 16;
    const uint32_t bIdx = (uint32_t)((lane & 7) + ((lane >> 4) & 1) * 8) * 144
                        + (uint32_t)((lane >> 3) & 1) * 16;

    float acc[12][4];
#pragma unroll
    for (int nt = 0; nt < 12; nt++)
#pragma unroll
        for (int i = 0; i < 4; i++) acc[nt][i] = 0.f;

    // prefetch registers
    float4 pa[8];
    uint4  pbh[6], pbl[6];

    // load chunk 0
#pragma unroll
    for (int q = 0; q < 8; q++) {
        int j = tid + 128 * q, row = j >> 4, seg = j & 15;
        pa[q] = *(const float4*)&x[(size_t)(m0 + row) * IN_ + seg * 4];
    }
#pragma unroll
    for (int q = 0; q < 6; q++) {
        int j = tid + 128 * q, row = j >> 3, seg = j & 7;
        pbh[q] = *(const uint4*)&g_k1bh[row * IN_ + seg * 8];
        pbl[q] = *(const uint4*)&g_k1bl[row * IN_ + seg * 8];
    }

    for (int c = 0; c < K1_CHUNKS; c++) {
        if (c > 0) __syncthreads();
        // STS tiles (A: split fp32 -> hi/lo)
#pragma unroll
        for (int q = 0; q < 8; q++) {
            int j = tid + 128 * q, row = j >> 4, seg = j & 15;
            __half h0, l0, h1, l1, h2, l2, h3, l3;
            split16(pa[q].x, h0, l0); split16(pa[q].y, h1, l1);
            split16(pa[q].z, h2, l2); split16(pa[q].w, h3, l3);
            *(uint32_t*)(smc + S1_AH + row * 144 + seg * 8)     = packh(h0, h1);
            *(uint32_t*)(smc + S1_AH + row * 144 + seg * 8 + 4) = packh(h2, h3);
            *(uint32_t*)(smc + S1_AL + row * 144 + seg * 8)     = packh(l0, l1);
            *(uint32_t*)(smc + S1_AL + row * 144 + seg * 8 + 4) = packh(l2, l3);
        }
#pragma unroll
        for (int q = 0; q < 6; q++) {
            int j = tid + 128 * q, row = j >> 3, seg = j & 7;
            *(uint4*)(smc + S1_BH + row * 144 + seg * 16) = pbh[q];
            *(uint4*)(smc + S1_BL + row * 144 + seg * 16) = pbl[q];
        }
        __syncthreads();
        // prefetch next chunk
        if (c + 1 < K1_CHUNKS) {
            int k0 = (c + 1) * 64;
#pragma unroll
            for (int q = 0; q < 8; q++) {
                int j = tid + 128 * q, row = j >> 4, seg = j & 15;
                pa[q] = *(const float4*)&x[(size_t)(m0 + row) * IN_ + k0 + seg * 4];
            }
#pragma unroll
            for (int q = 0; q < 6; q++) {
                int j = tid + 128 * q, row = j >> 3, seg = j & 7;
                pbh[q] = *(const uint4*)&g_k1bh[row * IN_ + k0 + seg * 8];
                pbl[q] = *(const uint4*)&g_k1bl[row * IN_ + k0 + seg * 8];
            }
        }
        // mma on current tiles
#pragma unroll
        for (int kt = 0; kt < 4; kt++) {
            uint32_t ah[4], al[4];
            ldsm4(ah, smb + S1_AH + aIdx + kt * 32);
            ldsm4(al, smb + S1_AL + aIdx + kt * 32);
            uint32_t bh[12][2], bl[12][2];
#pragma unroll
            for (int p = 0; p < 6; p++) {
                ldsm4(&bh[p * 2][0], smb + S1_BH + bIdx + p * 2304 + kt * 32);
                ldsm4(&bl[p * 2][0], smb + S1_BL + bIdx + p * 2304 + kt * 32);
            }
#pragma unroll
            for (int nt = 0; nt < 12; nt++) {
                mma16816(acc[nt], ah, bh[nt]);
                mma16816(acc[nt], ah, bl[nt]);
                mma16816(acc[nt], al, bh[nt]);
            }
        }
    }
    __syncthreads();

    // write C to smem (alias over tiles)
    {
        const int gid = lane >> 2, tc = lane & 3;
#pragma unroll
        for (int nt = 0; nt < 12; nt++) {
            int cc = nt * 8 + tc * 2;
            int r  = w * 16 + gid;
            Cs[r * 97 + cc]           = acc[nt][0];
            Cs[r * 97 + cc + 1]       = acc[nt][1];
            Cs[(r + 8) * 97 + cc]     = acc[nt][2];
            Cs[(r + 8) * 97 + cc + 1] = acc[nt][3];
        }
    }
    __syncthreads();

    // per-row scalar epilogue: threads 0..63 own row tid
    if (tid < 64) {
        const int base = tid * 97;
        const size_t gr = (size_t)(m0 + tid);

#pragma unroll 4
        for (int e = 0; e < 64; e++) {
            float v = Cs[base + e] + bias[e];
            Cs[base + e] = v > 0.f ? v : (__expf(v) - 1.0f);
        }
        float h[32];
#pragma unroll
        for (int j = 0; j < 32; j++) h[j] = bias[64 + j];
#pragma unroll 4
        for (int e = 0; e < 64; e++) {
            float ev = Cs[base + e];
#pragma unroll
            for (int j = 0; j < 32; j++) h[j] = fmaf(ev, mw2s[e * 32 + j], h[j]);
        }
#pragma unroll
        for (int j = 0; j < 32; j++) Cs[base + j] = h[j];

        float g[32], l[32];
#pragma unroll
        for (int j = 0; j < 32; j++) { g[j] = bias[96 + j]; l[j] = bias[128 + j]; }
#pragma unroll 2
        for (int i = 0; i < 32; i++) {
            float hv = Cs[base + i];
#pragma unroll
            for (int j = 0; j < 32; j++) {
                g[j] = fmaf(hv, mgws[i * 32 + j], g[j]);
                l[j] = fmaf(hv, mlw2s[i * 32 + j], l[j]);
            }
        }
        float pre[32];
#pragma unroll
        for (int j = 0; j < 32; j++) {
            float sig = 1.f / (1.f + __expf(-g[j]));
            pre[j] = fmaf(sig, l[j], Cs[base + 64 + j] + bias[160 + j]);
        }
        float mean = 0.f;
#pragma unroll
        for (int j = 0; j < 32; j++) mean += pre[j];
        mean *= (1.f / 32.f);
        float var = 0.f;
#pragma unroll
        for (int j = 0; j < 32; j++) { float d = pre[j] - mean; var = fmaf(d, d, var); }
        var *= (1.f / 32.f);
        float inv = rsqrtf(var + EPS_);
        float mx = -3.4e38f;
#pragma unroll
        for (int j = 0; j < 32; j++) {
            pre[j] = fmaf((pre[j] - mean) * inv, bias[192 + j], bias[224 + j]);
            mx = fmaxf(mx, pre[j]);
        }
        float ssum = 0.f;
#pragma unroll
        for (int j = 0; j < 32; j++) { pre[j] = __expf(pre[j] - mx); ssum += pre[j]; }
        float rinv = 1.f / ssum;
#pragma unroll
        for (int j = 0; j < 32; j++) {
            float mv = pre[j] * rinv;
            gmask[gr * 32 + j] = mv;
            if (out_mask) out_mask[gr * 32 + j] = mv;
        }
    }
}

// ===========================================================================
// Kernel 2: split-fp16 mma.sync GRN chain (R5, weights copied from g_k2w).
// ===========================================================================
#define SM_BIAS   0
#define SM_MSK    1536
#define SM_ACTH   2048
#define SM_ACTL   20480
#define SM_W0H    38912
#define SM_W0L    48128
#define SM_W1H    57344
#define SM_W1L    66560
#define SM_TOTAL  75776
#define ASTR_B    144
#define WSTR_B    144

__device__ __forceinline__ void copy_img(const __half* __restrict__ src, char* dst, int tid) {
#pragma unroll
    for (int q = 0; q < 5; q++) {
        int i = tid + 128 * q;
        if (i < 576) ((uint4*)dst)[i] = ((const uint4*)src)[i];
    }
}

__device__ __forceinline__ void gemm_full(uint32_t actH, uint32_t actL,
                                          uint32_t wtH, uint32_t wtL,
                                          uint32_t aIdx, uint32_t bIdx,
                                          float acc[8][2][4])
{
#pragma unroll
    for (int kt = 0; kt < 4; kt++) {
        uint32_t ah[2][4], al[2][4];
#pragma unroll
        for (int mt = 0; mt < 2; mt++) {
            ldsm4(ah[mt], actH + aIdx + mt * 2304 + kt * 32);
            ldsm4(al[mt], actL + aIdx + mt * 2304 + kt * 32);
        }
        uint32_t bh[8][2], bl[8][2];
#pragma unroll
        for (int p = 0; p < 4; p++) {
            ldsm4(&bh[p * 2][0], wtH + bIdx + p * 2304 + kt * 32);
            ldsm4(&bl[p * 2][0], wtL + bIdx + p * 2304 + kt * 32);
        }
#pragma unroll
        for (int nt = 0; nt < 8; nt++)
#pragma unroll
            for (int mt = 0; mt < 2; mt++) {
                mma16816(acc[nt][mt], ah[mt], bh[nt]);
                mma16816(acc[nt][mt], ah[mt], bl[nt]);
                mma16816(acc[nt][mt], al[mt], bh[nt]);
            }
    }
}

__device__ __forceinline__ void gemm_half(uint32_t actH, uint32_t actL,
                                          uint32_t gH, uint32_t gL,
                                          uint32_t lH, uint32_t lL,
                                          uint32_t aIdx, uint32_t bIdx, int h,
                                          float accg[4][2][4], float accl[4][2][4])
{
#pragma unroll
    for (int kt = 0; kt < 4; kt++) {
        uint32_t ah[2][4], al[2][4];
#pragma unroll
        for (int mt = 0; mt < 2; mt++) {
            ldsm4(ah[mt], actH + aIdx + mt * 2304 + kt * 32);
            ldsm4(al[mt], actL + aIdx + mt * 2304 + kt * 32);
        }
        uint32_t bgh[4][2], bgl[4][2], blh[4][2], bll[4][2];
#pragma unroll
        for (int q = 0; q < 2; q++) {
            int p = h * 2 + q;
            ldsm4(&bgh[q * 2][0], gH + bIdx + p * 2304 + kt * 32);
            ldsm4(&bgl[q * 2][0], gL + bIdx + p * 2304 + kt * 32);
            ldsm4(&blh[q * 2][0], lH + bIdx + p * 2304 + kt * 32);
            ldsm4(&bll[q * 2][0], lL + bIdx + p * 2304 + kt * 32);
        }
#pragma unroll
        for (int nt = 0; nt < 4; nt++)
#pragma unroll
            for (int mt = 0; mt < 2; mt++) {
                mma16816(accg[nt][mt], ah[mt], bgh[nt]);
                mma16816(accg[nt][mt], ah[mt], bgl[nt]);
                mma16816(accg[nt][mt], al[mt], bgh[nt]);
                mma16816(accl[nt][mt], ah[mt], blh[nt]);
                mma16816(accl[nt][mt], ah[mt], bll[nt]);
                mma16816(accl[nt][mt], al[mt], blh[nt]);
            }
    }
}

__global__ __launch_bounds__(128, 2)
void k2_grn_mma(const float* __restrict__ x,
                const float* __restrict__ b1, const float* __restrict__ b2,
                const float* __restrict__ gb, const float* __restrict__ lb,
                const float* __restrict__ gamma, const float* __restrict__ beta,
                const float* __restrict__ gmask, float* __restrict__ vbuf)
{
    extern __shared__ char smc[];
    const uint32_t smb = smem_u32(smc);
    float* bias = (float*)(smc + SM_BIAS);
    float* msk  = (float*)(smc + SM_MSK);

    const int tid  = threadIdx.x;
    const int lane = tid & 31;
    const int w    = tid >> 5;
    const int f    = blockIdx.x >> 7;
    const int r0c  = (blockIdx.x & 127) * 128;

    const uint32_t actH = smb + SM_ACTH, actL = smb + SM_ACTL;
    const uint32_t w0H  = smb + SM_W0H,  w0L  = smb + SM_W0L;
    const uint32_t w1H  = smb + SM_W1H,  w1L  = smb + SM_W1L;

    const uint32_t aIdx = ((uint32_t)(w * 32 + (lane & 15)) * 72 + (uint32_t)(lane >> 4) * 8) * 2;
    const uint32_t bIdx = ((uint32_t)((lane & 7) + ((lane >> 4) & 1) * 8)) * WSTR_B
                        + ((uint32_t)((lane >> 3) & 1)) * 16;

    if (tid < 64) {
        bias[tid]         = b1[f * 64 + tid];
        bias[64 + tid]    = b2[f * 64 + tid];
        bias[128 + tid]   = gb[f * 64 + tid];
        bias[192 + tid]   = lb[f * 64 + tid];
        bias[256 + tid]   = gamma[f * 64 + tid];
        bias[320 + tid]   = beta[f * 64 + tid];
    }
    msk[tid] = gmask[(size_t)(r0c + tid) * F_ + f];
#pragma unroll
    for (int q = 0; q < 16; q++) {
        int j   = tid + 128 * q;
        int row = j >> 4;
        int seg = j & 15;
        float4 v = *(const float4*)&x[((size_t)(r0c + row) * F_ + f) * 64 + seg * 4];
        __half h0, l0, h1, l1, h2, l2, h3, l3;
        split16(v.x, h0, l0); split16(v.y, h1, l1);
        split16(v.z, h2, l2); split16(v.w, h3, l3);
        *(uint32_t*)(smc + SM_ACTH + row * ASTR_B + seg * 8)     = packh(h0, h1);
        *(uint32_t*)(smc + SM_ACTH + row * ASTR_B + seg * 8 + 4) = packh(h2, h3);
        *(uint32_t*)(smc + SM_ACTL + row * ASTR_B + seg * 8)     = packh(l0, l1);
        *(uint32_t*)(smc + SM_ACTL + row * ASTR_B + seg * 8 + 4) = packh(l2, l3);
    }
    const __half* wimg = g_k2w + (size_t)(f * 4) * 2 * K2IMG;
    copy_img(wimg + 0 * K2IMG, smc + SM_W0H, tid);   // w1 hi
    copy_img(wimg + 1 * K2IMG, smc + SM_W0L, tid);   // w1 lo
    copy_img(wimg + 2 * K2IMG, smc + SM_W1H, tid);   // w2 hi
    copy_img(wimg + 3 * K2IMG, smc + SM_W1L, tid);   // w2 lo
    __syncthreads();

    const int gid = lane >> 2, tc = lane & 3;

    // ================= stage 1: hh1 = elu(x @ w1 + b1) =================
    {
        float acc[8][2][4];
#pragma unroll
        for (int nt = 0; nt < 8; nt++)
#pragma unroll
            for (int mt = 0; mt < 2; mt++)
#pragma unroll
                for (int i = 0; i < 4; i++) acc[nt][mt][i] = 0.f;
        gemm_full(actH, actL, w0H, w0L, aIdx, bIdx, acc);
        __syncthreads();
#pragma unroll
        for (int nt = 0; nt < 8; nt++) {
            int c = nt * 8 + tc * 2;
            float bb0 = bias[c], bb1 = bias[c + 1];
#pragma unroll
            for (int mt = 0; mt < 2; mt++) {
                int r0 = w * 32 + mt * 16 + gid;
#pragma unroll
                for (int jj = 0; jj < 2; jj++) {
                    int row = r0 + jj * 8;
                    float v0 = acc[nt][mt][jj * 2]     + bb0;
                    float v1 = acc[nt][mt][jj * 2 + 1] + bb1;
                    v0 = v0 > 0.f ? v0 : (__expf(v0) - 1.f);
                    v1 = v1 > 0.f ? v1 : (__expf(v1) - 1.f);
                    __half h0, l0, h1, l1;
                    split16(v0, h0, l0); split16(v1, h1, l1);
                    *(uint32_t*)(smc + SM_ACTH + row * ASTR_B + c * 2) = packh(h0, h1);
                    *(uint32_t*)(smc + SM_ACTL + row * ASTR_B + c * 2) = packh(l0, l1);
                }
            }
        }
        copy_img(wimg + 4 * K2IMG, smc + SM_W0H, tid);   // gw hi
        copy_img(wimg + 5 * K2IMG, smc + SM_W0L, tid);   // gw lo
    }
    __syncthreads();

    // ================= stage 2: hh2 = hh1 @ w2 + b2 =================
    {
        float acc[8][2][4];
#pragma unroll
        for (int nt = 0; nt < 8; nt++)
#pragma unroll
            for (int mt = 0; mt < 2; mt++)
#pragma unroll
                for (int i = 0; i < 4; i++) acc[nt][mt][i] = 0.f;
        gemm_full(actH, actL, w1H, w1L, aIdx, bIdx, acc);
        __syncthreads();
#pragma unroll
        for (int nt = 0; nt < 8; nt++) {
            int c = nt * 8 + tc * 2;
            float bb0 = bias[64 + c], bb1 = bias[64 + c + 1];
#pragma unroll
            for (int mt = 0; mt < 2; mt++) {
                int r0 = w * 32 + mt * 16 + gid;
#pragma unroll
                for (int jj = 0; jj < 2; jj++) {
                    int row = r0 + jj * 8;
                    float v0 = acc[nt][mt][jj * 2]     + bb0;
                    float v1 = acc[nt][mt][jj * 2 + 1] + bb1;
                    __half h0, l0, h1, l1;
                    split16(v0, h0, l0); split16(v1, h1, l1);
                    *(uint32_t*)(smc + SM_ACTH + row * ASTR_B + c * 2) = packh(h0, h1);
                    *(uint32_t*)(smc + SM_ACTL + row * ASTR_B + c * 2) = packh(l0, l1);
                }
            }
        }
        copy_img(wimg + 6 * K2IMG, smc + SM_W1H, tid);   // lw hi
        copy_img(wimg + 7 * K2IMG, smc + SM_W1L, tid);   // lw lo
    }
    __syncthreads();

    // ============ stage 3+4 fused, two n-halves; y + layernorm ============
    {
        float y[2][8][4];
        float s1[2][2] = {{0.f, 0.f}, {0.f, 0.f}};
        float s2[2][2] = {{0.f, 0.f}, {0.f, 0.f}};

#pragma unroll
        for (int h = 0; h < 2; h++) {
            float accg[4][2][4], accl[4][2][4];
#pragma unroll
            for (int nt = 0; nt < 4; nt++)
#pragma unroll
                for (int mt = 0; mt < 2; mt++)
#pragma unroll
                    for (int i = 0; i < 4; i++) { accg[nt][mt][i] = 0.f; accl[nt][mt][i] = 0.f; }
            gemm_half(actH, actL, w0H, w0L, w1H, w1L, aIdx, bIdx, h, accg, accl);
#pragma unroll
            for (int nt = 0; nt < 4; nt++) {
                int c = (h * 4 + nt) * 8 + tc * 2;
                float gb0 = bias[128 + c], gb1 = bias[128 + c + 1];
                float lb0 = bias[192 + c], lb1 = bias[192 + c + 1];
#pragma unroll
                for (int mt = 0; mt < 2; mt++) {
                    int r0 = w * 32 + mt * 16 + gid;
#pragma unroll
                    for (int jj = 0; jj < 2; jj++) {
                        int row = r0 + jj * 8;
                        const float2 xv = *(const float2*)&x[((size_t)(r0c + row) * F_ + f) * 64 + c];
                        float ga0 = accg[nt][mt][jj * 2]     + gb0;
                        float ga1 = accg[nt][mt][jj * 2 + 1] + gb1;
                        float la0 = accl[nt][mt][jj * 2]     + lb0;
                        float la1 = accl[nt][mt][jj * 2 + 1] + lb1;
                        float sg0 = 1.f / (1.f + __expf(-ga0));
                        float sg1 = 1.f / (1.f + __expf(-ga1));
                        float y0 = fmaf(sg0, la0, xv.x);
                        float y1 = fmaf(sg1, la1, xv.y);
                        y[mt][h * 4 + nt][jj * 2]     = y0;
                        y[mt][h * 4 + nt][jj * 2 + 1] = y1;
                        s1[mt][jj] += y0 + y1;
                        s2[mt][jj] = fmaf(y0, y0, fmaf(y1, y1, s2[mt][jj]));
                    }
                }
            }
        }

#pragma unroll
        for (int mt = 0; mt < 2; mt++)
#pragma unroll
            for (int jj = 0; jj < 2; jj++) {
#pragma unroll
                for (int o = 1; o < 4; o <<= 1) {
                    s1[mt][jj] += __shfl_xor_sync(0xFFFFFFFFu, s1[mt][jj], o);
                    s2[mt][jj] += __shfl_xor_sync(0xFFFFFFFFu, s2[mt][jj], o);
                }
            }

#pragma unroll
        for (int mt = 0; mt < 2; mt++) {
            int r0 = w * 32 + mt * 16 + gid;
#pragma unroll
            for (int jj = 0; jj < 2; jj++) {
                int row = r0 + jj * 8;
                float mean = s1[mt][jj] * (1.f / 64.f);
                float var  = fmaf(-mean, mean, s2[mt][jj] * (1.f / 64.f));
                float inv  = rsqrtf(var + EPS_);
                float mv   = msk[row];
                float* dstrow = &vbuf[((size_t)f * B_ + (size_t)(r0c + row)) * 64];
#pragma unroll
                for (int nt = 0; nt < 8; nt++) {
                    int c = nt * 8 + tc * 2;
                    float gm0 = bias[256 + c], gm1 = bias[256 + c + 1];
                    float bt0 = bias[320 + c], bt1 = bias[320 + c + 1];
                    float o0 = mv * fmaf((y[mt][nt][jj * 2]     - mean) * inv, gm0, bt0);
                    float o1 = mv * fmaf((y[mt][nt][jj * 2 + 1] - mean) * inv, gm1, bt1);
                    *(float2*)&dstrow[c] = make_float2(o0, o1);
                }
            }
        }
    }
}

// ===========================================================================
// Kernel 3: out[b,d] = sum_f vbuf[f,b,d]. Pure bandwidth (~268MB).
// ===========================================================================
#define K3_T 256
__global__ __launch_bounds__(K3_T, 4)
void k3_reduce_kernel(const float* __restrict__ vbuf, float* __restrict__ out)
{
    const size_t i4 = (size_t)blockIdx.x * K3_T + threadIdx.x;
    const size_t stride4 = (size_t)B_ * D_ / 4;
    const float4* vb = (const float4*)vbuf;
    float4 a = vb[i4];
#pragma unroll 4
    for (int f = 1; f < F_; f++) {
        float4 v = vb[i4 + (size_t)f * stride4];
        a.x += v.x; a.y += v.y; a.z += v.z; a.w += v.w;
    }
    ((float4*)out)[i4] = a;
}

// ===========================================================================
// Launcher
// ===========================================================================
extern "C" void kernel_launch(void* const* d_in, const int* in_sizes, int n_in,
                              void* d_out, int out_size)
{
    const float* x      = (const float*)d_in[0];
    const float* mw1    = (const float*)d_in[1];
    const float* mb1    = (const float*)d_in[2];
    const float* mw2    = (const float*)d_in[3];
    const float* mb2    = (const float*)d_in[4];
    const float* mlw    = (const float*)d_in[5];
    const float* mlb    = (const float*)d_in[6];
    const float* mgw    = (const float*)d_in[7];
    const float* mgb    = (const float*)d_in[8];
    const float* mlw2   = (const float*)d_in[9];
    const float* mlb2   = (const float*)d_in[10];
    const float* mgamma = (const float*)d_in[11];
    const float* mbeta  = (const float*)d_in[12];
    const float* w1     = (const float*)d_in[13];
    const float* b1     = (const float*)d_in[14];
    const float* w2     = (const float*)d_in[15];
    const float* b2     = (const float*)d_in[16];
    const float* gw     = (const float*)d_in[17];
    const float* gb     = (const float*)d_in[18];
    const float* lw     = (const float*)d_in[19];
    const float* lb     = (const float*)d_in[20];
    const float* gamma  = (const float*)d_in[21];
    const float* beta   = (const float*)d_in[22];

    float* out = (float*)d_out;
    float* out_mask = ((long long)out_size >= (long long)B_ * (64 + 32))
                          ? out + (size_t)B_ * 64 : nullptr;

    cudaFuncSetAttribute(k1_mask_mma, cudaFuncAttributeMaxDynamicSharedMemorySize, S1_TOTAL);
    cudaFuncSetAttribute(k2_grn_mma, cudaFuncAttributeMaxDynamicSharedMemorySize, SM_TOTAL);

    float* gmask_ptr = nullptr;
    float* vbuf_ptr  = nullptr;
    cudaGetSymbolAddress((void**)&gmask_ptr, g_mask_buf);
    cudaGetSymbolAddress((void**)&vbuf_ptr,  g_vbuf);

    // weight pre-splits
    k0a_split_k1w<<<(96 * IN_ + 255) / 256, 256>>>(mw1, mlw);
    k0b_split_k2w<<<(F_ * 4 * 4096 + 255) / 256, 256>>>(w1, w2, gw, lw);

    k1_mask_mma<<<B_ / 64, 128, S1_TOTAL>>>(x, mb1, mw2, mb2, mlb,
                                            mgw, mgb, mlw2, mlb2, mgamma, mbeta,
                                            gmask_ptr, out_mask);
    k2_grn_mma<<<F_ * (B_ / 128), 128, SM_TOTAL>>>(x, b1, b2, gb, lb, gamma, beta,
                                                   gmask_ptr, vbuf_ptr);
    k3_reduce_kernel<<<(B_ * D_ / 4) / K3_T, K3_T>>>(vbuf_ptr, out);
}

// round 7
// speedup vs baseline: 2.9908x; 1.0908x over previous
#include <cuda_runtime.h>
#include <cuda_bf16.h>
#include <cuda_fp16.h>
#include <math.h>
#include <stdint.h>

// Problem constants
#define B_  16384
#define F_  32
#define D_  64
#define IN_ 2048   // F_*D_
#define EPS_ 1e-5f

// ---------------------------------------------------------------------------
// Scratch (no device mallocs allowed)
// ---------------------------------------------------------------------------
__device__ float g_mask_buf[(size_t)B_ * F_];
__device__ float g_vbuf[(size_t)F_ * B_ * D_];
// k1 weights, split fp16, transposed [n=96][k=2048]
__device__ __align__(16) __half g_k1bh[96 * IN_];
__device__ __align__(16) __half g_k1bl[96 * IN_];
// k2 weights: per (f, matrix m in {w1,w2,gw,lw}, hi/lo) a 64x72-half smem image
#define K2IMG 4608   // 64*72 halfs
__device__ __align__(16) __half g_k2w[(size_t)F_ * 4 * 2 * K2IMG];

// ---------------------------------------------------------------------------
// helpers
// ---------------------------------------------------------------------------
__device__ __forceinline__ uint32_t smem_u32(const void* p) {
    uint32_t a;
    asm("{ .reg .u64 t; cvta.to.shared.u64 t, %1; cvt.u32.u64 %0, t; }" : "=r"(a) : "l"(p));
    return a;
}
__device__ __forceinline__ void ldsm4(uint32_t* r, uint32_t a) {
    asm volatile("ldmatrix.sync.aligned.m8n8.x4.shared.b16 {%0,%1,%2,%3}, [%4];"
        : "=r"(r[0]), "=r"(r[1]), "=r"(r[2]), "=r"(r[3]) : "r"(a));
}
__device__ __forceinline__ void mma16816(float* d, const uint32_t* a, const uint32_t* b) {
    asm volatile("mma.sync.aligned.m16n8k16.row.col.f32.f16.f16.f32 "
        "{%0,%1,%2,%3},{%4,%5,%6,%7},{%8,%9},{%0,%1,%2,%3};"
        : "+f"(d[0]), "+f"(d[1]), "+f"(d[2]), "+f"(d[3])
        : "r"(a[0]), "r"(a[1]), "r"(a[2]), "r"(a[3]), "r"(b[0]), "r"(b[1]));
}
__device__ __forceinline__ uint32_t packh(__half a, __half b) {
    __half2 t = __halves2half2(a, b);
    return *(uint32_t*)&t;
}
__device__ __forceinline__ void split16(float v, __half& h, __half& l) {
    h = __float2half_rn(v);
    l = __float2half_rn(v - __half2float(h));
}

// ===========================================================================
// Kernel 0a: split k1 weights into g_k1bh/g_k1bl, transposed [n][k].
// ===========================================================================
__global__ void k0a_split_k1w(const float* __restrict__ mw1,
                              const float* __restrict__ mlw)
{
    int idx = blockIdx.x * 256 + threadIdx.x;      // 96*2048 total
    if (idx >= 96 * IN_) return;
    int n = idx >> 11, k = idx & (IN_ - 1);
    float v = (n < 64) ? mw1[(size_t)k * 64 + n] : mlw[(size_t)k * 32 + (n - 64)];
    __half h, l; split16(v, h, l);
    g_k1bh[idx] = h;
    g_k1bl[idx] = l;
}

// ===========================================================================
// Kernel 0b: split k2 weights into ready 64x72-half smem images (hi/lo).
// ===========================================================================
__global__ void k0b_split_k2w(const float* __restrict__ w1, const float* __restrict__ w2,
                              const float* __restrict__ gw, const float* __restrict__ lw)
{
    int idx = blockIdx.x * 256 + threadIdx.x;      // 32*4*4096 total
    if (idx >= F_ * 4 * 4096) return;
    int f = idx >> 14, m = (idx >> 12) & 3, e = (idx >> 6) & 63, d = idx & 63;
    const float* W = (m == 0) ? w1 : (m == 1) ? w2 : (m == 2) ? gw : lw;
    float v = W[(size_t)f * 4096 + d * 64 + e];
    __half h, l; split16(v, h, l);
    size_t base = ((size_t)(f * 4 + m)) * 2 * K2IMG;
    g_k2w[base + e * 72 + d] = h;
    g_k2w[base + K2IMG + e * 72 + d] = l;
}

// ===========================================================================
// Kernel 1 (tensor): mask branch. BM=64 rows/CTA, 128 threads, 256 CTAs.
// (unchanged from R6 — ~95us)
// ===========================================================================
#define S1_AH   0
#define S1_AL   9216
#define S1_BH   18432
#define S1_BL   32256
#define S1_EPI  46080
#define S1_MGW  (S1_EPI + 8192)
#define S1_MLW2 (S1_MGW + 4096)
#define S1_BIAS (S1_MLW2 + 4096)
#define S1_TOTAL (S1_BIAS + 1024)
#define K1_CHUNKS (IN_ / 64)

__global__ __launch_bounds__(128, 2)
void k1_mask_mma(const float* __restrict__ x,
                 const float* __restrict__ mb1,
                 const float* __restrict__ mw2, const float* __restrict__ mb2,
                 const float* __restrict__ mlb,
                 const float* __restrict__ mgw, const float* __restrict__ mgb,
                 const float* __restrict__ mlw2, const float* __restrict__ mlb2,
                 const float* __restrict__ mgamma, const float* __restrict__ mbeta,
                 float* __restrict__ gmask, float* __restrict__ out_mask)
{
    extern __shared__ char smc[];
    const uint32_t smb = smem_u32(smc);
    float* Cs    = (float*)smc;
    float* mw2s  = (float*)(smc + S1_EPI);
    float* mgws  = (float*)(smc + S1_MGW);
    float* mlw2s = (float*)(smc + S1_MLW2);
    float* bias  = (float*)(smc + S1_BIAS);

    const int tid  = threadIdx.x;
    const int lane = tid & 31;
    const int w    = tid >> 5;
    const int m0   = blockIdx.x * 64;

    for (int i = tid; i < 2048; i += 128) mw2s[i] = mw2[i];
    for (int i = tid; i < 1024; i += 128) { mgws[i] = mgw[i]; mlw2s[i] = mlw2[i]; }
    if (tid < 64) bias[tid] = mb1[tid];
    if (tid < 32) {
        bias[64 + tid]  = mb2[tid];   bias[96 + tid]  = mgb[tid];
        bias[128 + tid] = mlb2[tid];  bias[160 + tid] = mlb[tid];
        bias[192 + tid] = mgamma[tid]; bias[224 + tid] = mbeta[tid];
    }

    const uint32_t aIdx = (uint32_t)(w * 16 + (lane & 15)) * 144 + (uint32_t)(lane >> 4) * 16;
    const uint32_t bIdx = (uint32_t)((lane & 7) + ((lane >> 4) & 1) * 8) * 144
                        + (uint32_t)((lane >> 3) & 1) * 16;

    float acc[12][4];
#pragma unroll
    for (int nt = 0; nt < 12; nt++)
#pragma unroll
        for (int i = 0; i < 4; i++) acc[nt][i] = 0.f;

    float4 pa[8];
    uint4  pbh[6], pbl[6];

#pragma unroll
    for (int q = 0; q < 8; q++) {
        int j = tid + 128 * q, row = j >> 4, seg = j & 15;
        pa[q] = *(const float4*)&x[(size_t)(m0 + row) * IN_ + seg * 4];
    }
#pragma unroll
    for (int q = 0; q < 6; q++) {
        int j = tid + 128 * q, row = j >> 3, seg = j & 7;
        pbh[q] = *(const uint4*)&g_k1bh[row * IN_ + seg * 8];
        pbl[q] = *(const uint4*)&g_k1bl[row * IN_ + seg * 8];
    }

    for (int c = 0; c < K1_CHUNKS; c++) {
        if (c > 0) __syncthreads();
#pragma unroll
        for (int q = 0; q < 8; q++) {
            int j = tid + 128 * q, row = j >> 4, seg = j & 15;
            __half h0, l0, h1, l1, h2, l2, h3, l3;
            split16(pa[q].x, h0, l0); split16(pa[q].y, h1, l1);
            split16(pa[q].z, h2, l2); split16(pa[q].w, h3, l3);
            *(uint32_t*)(smc + S1_AH + row * 144 + seg * 8)     = packh(h0, h1);
            *(uint32_t*)(smc + S1_AH + row * 144 + seg * 8 + 4) = packh(h2, h3);
            *(uint32_t*)(smc + S1_AL + row * 144 + seg * 8)     = packh(l0, l1);
            *(uint32_t*)(smc + S1_AL + row * 144 + seg * 8 + 4) = packh(l2, l3);
        }
#pragma unroll
        for (int q = 0; q < 6; q++) {
            int j = tid + 128 * q, row = j >> 3, seg = j & 7;
            *(uint4*)(smc + S1_BH + row * 144 + seg * 16) = pbh[q];
            *(uint4*)(smc + S1_BL + row * 144 + seg * 16) = pbl[q];
        }
        __syncthreads();
        if (c + 1 < K1_CHUNKS) {
            int k0 = (c + 1) * 64;
#pragma unroll
            for (int q = 0; q < 8; q++) {
                int j = tid + 128 * q, row = j >> 4, seg = j & 15;
                pa[q] = *(const float4*)&x[(size_t)(m0 + row) * IN_ + k0 + seg * 4];
            }
#pragma unroll
            for (int q = 0; q < 6; q++) {
                int j = tid + 128 * q, row = j >> 3, seg = j & 7;
                pbh[q] = *(const uint4*)&g_k1bh[row * IN_ + k0 + seg * 8];
                pbl[q] = *(const uint4*)&g_k1bl[row * IN_ + k0 + seg * 8];
            }
        }
#pragma unroll
        for (int kt = 0; kt < 4; kt++) {
            uint32_t ah[4], al[4];
            ldsm4(ah, smb + S1_AH + aIdx + kt * 32);
            ldsm4(al, smb + S1_AL + aIdx + kt * 32);
            uint32_t bh[12][2], bl[12][2];
#pragma unroll
            for (int p = 0; p < 6; p++) {
                ldsm4(&bh[p * 2][0], smb + S1_BH + bIdx + p * 2304 + kt * 32);
                ldsm4(&bl[p * 2][0], smb + S1_BL + bIdx + p * 2304 + kt * 32);
            }
#pragma unroll
            for (int nt = 0; nt < 12; nt++) {
                mma16816(acc[nt], ah, bh[nt]);
                mma16816(acc[nt], ah, bl[nt]);
                mma16816(acc[nt], al, bh[nt]);
            }
        }
    }
    __syncthreads();

    {
        const int gid = lane >> 2, tc = lane & 3;
#pragma unroll
        for (int nt = 0; nt < 12; nt++) {
            int cc = nt * 8 + tc * 2;
            int r  = w * 16 + gid;
            Cs[r * 97 + cc]           = acc[nt][0];
            Cs[r * 97 + cc + 1]       = acc[nt][1];
            Cs[(r + 8) * 97 + cc]     = acc[nt][2];
            Cs[(r + 8) * 97 + cc + 1] = acc[nt][3];
        }
    }
    __syncthreads();

    if (tid < 64) {
        const int base = tid * 97;
        const size_t gr = (size_t)(m0 + tid);

#pragma unroll 4
        for (int e = 0; e < 64; e++) {
            float v = Cs[base + e] + bias[e];
            Cs[base + e] = v > 0.f ? v : (__expf(v) - 1.0f);
        }
        float h[32];
#pragma unroll
        for (int j = 0; j < 32; j++) h[j] = bias[64 + j];
#pragma unroll 4
        for (int e = 0; e < 64; e++) {
            float ev = Cs[base + e];
#pragma unroll
            for (int j = 0; j < 32; j++) h[j] = fmaf(ev, mw2s[e * 32 + j], h[j]);
        }
#pragma unroll
        for (int j = 0; j < 32; j++) Cs[base + j] = h[j];

        float g[32], l[32];
#pragma unroll
        for (int j = 0; j < 32; j++) { g[j] = bias[96 + j]; l[j] = bias[128 + j]; }
#pragma unroll 2
        for (int i = 0; i < 32; i++) {
            float hv = Cs[base + i];
#pragma unroll
            for (int j = 0; j < 32; j++) {
                g[j] = fmaf(hv, mgws[i * 32 + j], g[j]);
                l[j] = fmaf(hv, mlw2s[i * 32 + j], l[j]);
            }
        }
        float pre[32];
#pragma unroll
        for (int j = 0; j < 32; j++) {
            float sig = 1.f / (1.f + __expf(-g[j]));
            pre[j] = fmaf(sig, l[j], Cs[base + 64 + j] + bias[160 + j]);
        }
        float mean = 0.f;
#pragma unroll
        for (int j = 0; j < 32; j++) mean += pre[j];
        mean *= (1.f / 32.f);
        float var = 0.f;
#pragma unroll
        for (int j = 0; j < 32; j++) { float d = pre[j] - mean; var = fmaf(d, d, var); }
        var *= (1.f / 32.f);
        float inv = rsqrtf(var + EPS_);
        float mx = -3.4e38f;
#pragma unroll
        for (int j = 0; j < 32; j++) {
            pre[j] = fmaf((pre[j] - mean) * inv, bias[192 + j], bias[224 + j]);
            mx = fmaxf(mx, pre[j]);
        }
        float ssum = 0.f;
#pragma unroll
        for (int j = 0; j < 32; j++) { pre[j] = __expf(pre[j] - mx); ssum += pre[j]; }
        float rinv = 1.f / ssum;
#pragma unroll
        for (int j = 0; j < 32; j++) {
            float mv = pre[j] * rinv;
            gmask[gr * 32 + j] = mv;
            if (out_mask) out_mask[gr * 32 + j] = mv;
        }
    }
}

// ===========================================================================
// Kernel 2: split-fp16 mma.sync GRN chain — NOW 256 threads / 8 warps.
// Warp w owns rows w*16..w*16+15 (full 64 cols). Same smem layout as R6.
// ===========================================================================
#define SM_BIAS   0
#define SM_MSK    1536
#define SM_ACTH   2048
#define SM_ACTL   20480
#define SM_W0H    38912
#define SM_W0L    48128
#define SM_W1H    57344
#define SM_W1L    66560
#define SM_TOTAL  75776
#define ASTR_B    144
#define WSTR_B    144
#define T2        256

__device__ __forceinline__ void copy_img(const __half* __restrict__ src, char* dst, int tid) {
#pragma unroll
    for (int q = 0; q < 3; q++) {
        int i = tid + T2 * q;
        if (i < 576) ((uint4*)dst)[i] = ((const uint4*)src)[i];
    }
}

__device__ __forceinline__ void gemm_full(uint32_t actH, uint32_t actL,
                                          uint32_t wtH, uint32_t wtL,
                                          uint32_t aIdx, uint32_t bIdx,
                                          float acc[8][4])
{
#pragma unroll
    for (int kt = 0; kt < 4; kt++) {
        uint32_t ah[4], al[4];
        ldsm4(ah, actH + aIdx + kt * 32);
        ldsm4(al, actL + aIdx + kt * 32);
        uint32_t bh[8][2], bl[8][2];
#pragma unroll
        for (int p = 0; p < 4; p++) {
            ldsm4(&bh[p * 2][0], wtH + bIdx + p * 2304 + kt * 32);
            ldsm4(&bl[p * 2][0], wtL + bIdx + p * 2304 + kt * 32);
        }
#pragma unroll
        for (int nt = 0; nt < 8; nt++) {
            mma16816(acc[nt], ah, bh[nt]);
            mma16816(acc[nt], ah, bl[nt]);
            mma16816(acc[nt], al, bh[nt]);
        }
    }
}

__device__ __forceinline__ void gemm_half(uint32_t actH, uint32_t actL,
                                          uint32_t gH, uint32_t gL,
                                          uint32_t lH, uint32_t lL,
                                          uint32_t aIdx, uint32_t bIdx, int h,
                                          float accg[4][4], float accl[4][4])
{
#pragma unroll
    for (int kt = 0; kt < 4; kt++) {
        uint32_t ah[4], al[4];
        ldsm4(ah, actH + aIdx + kt * 32);
        ldsm4(al, actL + aIdx + kt * 32);
        uint32_t bgh[4][2], bgl[4][2], blh[4][2], bll[4][2];
#pragma unroll
        for (int q = 0; q < 2; q++) {
            int p = h * 2 + q;
            ldsm4(&bgh[q * 2][0], gH + bIdx + p * 2304 + kt * 32);
            ldsm4(&bgl[q * 2][0], gL + bIdx + p * 2304 + kt * 32);
            ldsm4(&blh[q * 2][0], lH + bIdx + p * 2304 + kt * 32);
            ldsm4(&bll[q * 2][0], lL + bIdx + p * 2304 + kt * 32);
        }
#pragma unroll
        for (int nt = 0; nt < 4; nt++) {
            mma16816(accg[nt], ah, bgh[nt]);
            mma16816(accg[nt], ah, bgl[nt]);
            mma16816(accg[nt], al, bgh[nt]);
            mma16816(accl[nt], ah, blh[nt]);
            mma16816(accl[nt], ah, bll[nt]);
            mma16816(accl[nt], al, blh[nt]);
        }
    }
}

__global__ __launch_bounds__(T2, 2)
void k2_grn_mma(const float* __restrict__ x,
                const float* __restrict__ b1, const float* __restrict__ b2,
                const float* __restrict__ gb, const float* __restrict__ lb,
                const float* __restrict__ gamma, const float* __restrict__ beta,
                const float* __restrict__ gmask, float* __restrict__ vbuf)
{
    extern __shared__ char smc[];
    const uint32_t smb = smem_u32(smc);
    float* bias = (float*)(smc + SM_BIAS);
    float* msk  = (float*)(smc + SM_MSK);

    const int tid  = threadIdx.x;
    const int lane = tid & 31;
    const int w    = tid >> 5;     // 0..7
    const int f    = blockIdx.x >> 7;
    const int r0c  = (blockIdx.x & 127) * 128;

    const uint32_t actH = smb + SM_ACTH, actL = smb + SM_ACTL;
    const uint32_t w0H  = smb + SM_W0H,  w0L  = smb + SM_W0L;
    const uint32_t w1H  = smb + SM_W1H,  w1L  = smb + SM_W1L;

    const uint32_t aIdx = (uint32_t)(w * 16 + (lane & 15)) * ASTR_B + (uint32_t)(lane >> 4) * 16;
    const uint32_t bIdx = ((uint32_t)((lane & 7) + ((lane >> 4) & 1) * 8)) * WSTR_B
                        + ((uint32_t)((lane >> 3) & 1)) * 16;

    if (tid < 64) {
        bias[tid]         = b1[f * 64 + tid];
        bias[64 + tid]    = b2[f * 64 + tid];
        bias[128 + tid]   = gb[f * 64 + tid];
        bias[192 + tid]   = lb[f * 64 + tid];
        bias[256 + tid]   = gamma[f * 64 + tid];
        bias[320 + tid]   = beta[f * 64 + tid];
    }
    if (tid < 128) msk[tid] = gmask[(size_t)(r0c + tid) * F_ + f];
#pragma unroll
    for (int q = 0; q < 8; q++) {
        int j   = tid + T2 * q;
        int row = j >> 4;
        int seg = j & 15;
        float4 v = *(const float4*)&x[((size_t)(r0c + row) * F_ + f) * 64 + seg * 4];
        __half h0, l0, h1, l1, h2, l2, h3, l3;
        split16(v.x, h0, l0); split16(v.y, h1, l1);
        split16(v.z, h2, l2); split16(v.w, h3, l3);
        *(uint32_t*)(smc + SM_ACTH + row * ASTR_B + seg * 8)     = packh(h0, h1);
        *(uint32_t*)(smc + SM_ACTH + row * ASTR_B + seg * 8 + 4) = packh(h2, h3);
        *(uint32_t*)(smc + SM_ACTL + row * ASTR_B + seg * 8)     = packh(l0, l1);
        *(uint32_t*)(smc + SM_ACTL + row * ASTR_B + seg * 8 + 4) = packh(l2, l3);
    }
    const __half* wimg = g_k2w + (size_t)(f * 4) * 2 * K2IMG;
    copy_img(wimg + 0 * K2IMG, smc + SM_W0H, tid);
    copy_img(wimg + 1 * K2IMG, smc + SM_W0L, tid);
    copy_img(wimg + 2 * K2IMG, smc + SM_W1H, tid);
    copy_img(wimg + 3 * K2IMG, smc + SM_W1L, tid);
    __syncthreads();

    const int gid = lane >> 2, tc = lane & 3;

    // ================= stage 1: hh1 = elu(x @ w1 + b1) =================
    {
        float acc[8][4];
#pragma unroll
        for (int nt = 0; nt < 8; nt++)
#pragma unroll
            for (int i = 0; i < 4; i++) acc[nt][i] = 0.f;
        gemm_full(actH, actL, w0H, w0L, aIdx, bIdx, acc);
        __syncthreads();
#pragma unroll
        for (int nt = 0; nt < 8; nt++) {
            int c = nt * 8 + tc * 2;
            float bb0 = bias[c], bb1 = bias[c + 1];
#pragma unroll
            for (int jj = 0; jj < 2; jj++) {
                int row = w * 16 + gid + jj * 8;
                float v0 = acc[nt][jj * 2]     + bb0;
                float v1 = acc[nt][jj * 2 + 1] + bb1;
                v0 = v0 > 0.f ? v0 : (__expf(v0) - 1.f);
                v1 = v1 > 0.f ? v1 : (__expf(v1) - 1.f);
                __half h0, l0, h1, l1;
                split16(v0, h0, l0); split16(v1, h1, l1);
                *(uint32_t*)(smc + SM_ACTH + row * ASTR_B + c * 2) = packh(h0, h1);
                *(uint32_t*)(smc + SM_ACTL + row * ASTR_B + c * 2) = packh(l0, l1);
            }
        }
        copy_img(wimg + 4 * K2IMG, smc + SM_W0H, tid);
        copy_img(wimg + 5 * K2IMG, smc + SM_W0L, tid);
    }
    __syncthreads();

    // ================= stage 2: hh2 = hh1 @ w2 + b2 =================
    {
        float acc[8][4];
#pragma unroll
        for (int nt = 0; nt < 8; nt++)
#pragma unroll
            for (int i = 0; i < 4; i++) acc[nt][i] = 0.f;
        gemm_full(actH, actL, w1H, w1L, aIdx, bIdx, acc);
        __syncthreads();
#pragma unroll
        for (int nt = 0; nt < 8; nt++) {
            int c = nt * 8 + tc * 2;
            float bb0 = bias[64 + c], bb1 = bias[64 + c + 1];
#pragma unroll
            for (int jj = 0; jj < 2; jj++) {
                int row = w * 16 + gid + jj * 8;
                float v0 = acc[nt][jj * 2]     + bb0;
                float v1 = acc[nt][jj * 2 + 1] + bb1;
                __half h0, l0, h1, l1;
                split16(v0, h0, l0); split16(v1, h1, l1);
                *(uint32_t*)(smc + SM_ACTH + row * ASTR_B + c * 2) = packh(h0, h1);
                *(uint32_t*)(smc + SM_ACTL + row * ASTR_B + c * 2) = packh(l0, l1);
            }
        }
        copy_img(wimg + 6 * K2IMG, smc + SM_W1H, tid);
        copy_img(wimg + 7 * K2IMG, smc + SM_W1L, tid);
    }
    __syncthreads();

    // ============ stage 3+4 fused, two n-halves; y + layernorm ============
    {
        float y[8][4];
        float s1[2] = {0.f, 0.f};
        float s2[2] = {0.f, 0.f};

#pragma unroll
        for (int h = 0; h < 2; h++) {
            float accg[4][4], accl[4][4];
#pragma unroll
            for (int nt = 0; nt < 4; nt++)
#pragma unroll
                for (int i = 0; i < 4; i++) { accg[nt][i] = 0.f; accl[nt][i] = 0.f; }
            gemm_half(actH, actL, w0H, w0L, w1H, w1L, aIdx, bIdx, h, accg, accl);
#pragma unroll
            for (int nt = 0; nt < 4; nt++) {
                int c = (h * 4 + nt) * 8 + tc * 2;
                float gb0 = bias[128 + c], gb1 = bias[128 + c + 1];
                float lb0 = bias[192 + c], lb1 = bias[192 + c + 1];
#pragma unroll
                for (int jj = 0; jj < 2; jj++) {
                    int row = w * 16 + gid + jj * 8;
                    const float2 xv = *(const float2*)&x[((size_t)(r0c + row) * F_ + f) * 64 + c];
                    float ga0 = accg[nt][jj * 2]     + gb0;
                    float ga1 = accg[nt][jj * 2 + 1] + gb1;
                    float la0 = accl[nt][jj * 2]     + lb0;
                    float la1 = accl[nt][jj * 2 + 1] + lb1;
                    float sg0 = 1.f / (1.f + __expf(-ga0));
                    float sg1 = 1.f / (1.f + __expf(-ga1));
                    float y0 = fmaf(sg0, la0, xv.x);
                    float y1 = fmaf(sg1, la1, xv.y);
                    y[h * 4 + nt][jj * 2]     = y0;
                    y[h * 4 + nt][jj * 2 + 1] = y1;
                    s1[jj] += y0 + y1;
                    s2[jj] = fmaf(y0, y0, fmaf(y1, y1, s2[jj]));
                }
            }
        }

#pragma unroll
        for (int jj = 0; jj < 2; jj++) {
#pragma unroll
            for (int o = 1; o < 4; o <<= 1) {
                s1[jj] += __shfl_xor_sync(0xFFFFFFFFu, s1[jj], o);
                s2[jj] += __shfl_xor_sync(0xFFFFFFFFu, s2[jj], o);
            }
        }

#pragma unroll
        for (int jj = 0; jj < 2; jj++) {
            int row = w * 16 + gid + jj * 8;
            float mean = s1[jj] * (1.f / 64.f);
            float var  = fmaf(-mean, mean, s2[jj] * (1.f / 64.f));
            float inv  = rsqrtf(var + EPS_);
            float mv   = msk[row];
            float* dstrow = &vbuf[((size_t)f * B_ + (size_t)(r0c + row)) * 64];
#pragma unroll
            for (int nt = 0; nt < 8; nt++) {
                int c = nt * 8 + tc * 2;
                float gm0 = bias[256 + c], gm1 = bias[256 + c + 1];
                float bt0 = bias[320 + c], bt1 = bias[320 + c + 1];
                float o0 = mv * fmaf((y[nt][jj * 2]     - mean) * inv, gm0, bt0);
                float o1 = mv * fmaf((y[nt][jj * 2 + 1] - mean) * inv, gm1, bt1);
                *(float2*)&dstrow[c] = make_float2(o0, o1);
            }
        }
    }
}

// ===========================================================================
// Kernel 3: out[b,d] = sum_f vbuf[f,b,d]. Pure bandwidth (~268MB).
// ===========================================================================
#define K3_T 256
__global__ __launch_bounds__(K3_T, 4)
void k3_reduce_kernel(const float* __restrict__ vbuf, float* __restrict__ out)
{
    const size_t i4 = (size_t)blockIdx.x * K3_T + threadIdx.x;
    const size_t stride4 = (size_t)B_ * D_ / 4;
    const float4* vb = (const float4*)vbuf;
    float4 a = vb[i4];
#pragma unroll 4
    for (int f = 1; f < F_; f++) {
        float4 v = vb[i4 + (size_t)f * stride4];
        a.x += v.x; a.y += v.y; a.z += v.z; a.w += v.w;
    }
    ((float4*)out)[i4] = a;
}

// ===========================================================================
// Launcher
// ===========================================================================
extern "C" void kernel_launch(void* const* d_in, const int* in_sizes, int n_in,
                              void* d_out, int out_size)
{
    const float* x      = (const float*)d_in[0];
    const float* mw1    = (const float*)d_in[1];
    const float* mb1    = (const float*)d_in[2];
    const float* mw2    = (const float*)d_in[3];
    const float* mb2    = (const float*)d_in[4];
    const float* mlw    = (const float*)d_in[5];
    const float* mlb    = (const float*)d_in[6];
    const float* mgw    = (const float*)d_in[7];
    const float* mgb    = (const float*)d_in[8];
    const float* mlw2   = (const float*)d_in[9];
    const float* mlb2   = (const float*)d_in[10];
    const float* mgamma = (const float*)d_in[11];
    const float* mbeta  = (const float*)d_in[12];
    const float* w1     = (const float*)d_in[13];
    const float* b1     = (const float*)d_in[14];
    const float* w2     = (const float*)d_in[15];
    const float* b2     = (const float*)d_in[16];
    const float* gw     = (const float*)d_in[17];
    const float* gb     = (const float*)d_in[18];
    const float* lw     = (const float*)d_in[19];
    const float* lb     = (const float*)d_in[20];
    const float* gamma  = (const float*)d_in[21];
    const float* beta   = (const float*)d_in[22];

    float* out = (float*)d_out;
    float* out_mask = ((long long)out_size >= (long long)B_ * (64 + 32))
                          ? out + (size_t)B_ * 64 : nullptr;

    cudaFuncSetAttribute(k1_mask_mma, cudaFuncAttributeMaxDynamicSharedMemorySize, S1_TOTAL);
    cudaFuncSetAttribute(k2_grn_mma, cudaFuncAttributeMaxDynamicSharedMemorySize, SM_TOTAL);

    float* gmask_ptr = nullptr;
    float* vbuf_ptr  = nullptr;
    cudaGetSymbolAddress((void**)&gmask_ptr, g_mask_buf);
    cudaGetSymbolAddress((void**)&vbuf_ptr,  g_vbuf);

    k0a_split_k1w<<<(96 * IN_ + 255) / 256, 256>>>(mw1, mlw);
    k0b_split_k2w<<<(F_ * 4 * 4096 + 255) / 256, 256>>>(w1, w2, gw, lw);

    k1_mask_mma<<<B_ / 64, 128, S1_TOTAL>>>(x, mb1, mw2, mb2, mlb,
                                            mgw, mgb, mlw2, mlb2, mgamma, mbeta,
                                            gmask_ptr, out_mask);
    k2_grn_mma<<<F_ * (B_ / 128), T2, SM_TOTAL>>>(x, b1, b2, gb, lb, gamma, beta,
                                                  gmask_ptr, vbuf_ptr);
    k3_reduce_kernel<<<(B_ * D_ / 4) / K3_T, K3_T>>>(vbuf_ptr, out);
}